// round 1
// baseline (speedup 1.0000x reference)
#include <cuda_runtime.h>
#include <math.h>

#define BATCH 4
#define SEQ   2048
#define DIM   768
#define HEADS 12
#define HS    64
#define MTOT  (BATCH*SEQ)

// Scratch (allocation-free: __device__ globals)
static __device__ float g_Q[BATCH*HEADS*SEQ*HS];
static __device__ float g_K[BATCH*HEADS*SEQ*HS];
static __device__ float g_V[BATCH*HEADS*SEQ*HS];
static __device__ float g_A[MTOT*DIM];

// ---------------------------------------------------------------------------
// SGEMM: C = (A[M,K] @ B[K,N] + bias) * scale
// mode 0: C[m*N+n] plain   mode 1: headed layout [B,HEADS,SEQ,HS]
// 128x128 tile, BK=8, 256 threads, 8x8 microtile
// ---------------------------------------------------------------------------
__global__ __launch_bounds__(256)
void sgemm_bias(const float* __restrict__ A, const float* __restrict__ B,
                const float* __restrict__ bias, float* __restrict__ C,
                int mode, float scale)
{
    const int N = DIM, K = DIM;
    __shared__ float As[8][128];
    __shared__ float Bs[8][128];
    const int tid = threadIdx.x;
    const int m0 = blockIdx.y * 128;
    const int n0 = blockIdx.x * 128;
    const int ty = tid >> 4, tx = tid & 15;
    const int i0 = ty * 8, j0 = tx * 8;
    const int arow = tid >> 1, akc = (tid & 1) * 4;
    const int brow = tid >> 5, bnc = (tid & 31) * 4;

    float acc[8][8];
#pragma unroll
    for (int i = 0; i < 8; i++)
#pragma unroll
        for (int j = 0; j < 8; j++) acc[i][j] = 0.f;

    const float* Aptr = A + (m0 + arow) * K + akc;
    const float* Bptr = B + brow * N + n0 + bnc;

    for (int k0 = 0; k0 < K; k0 += 8) {
        float4 av = *(const float4*)(Aptr + k0);
        float4 bv = *(const float4*)(Bptr + k0 * N);
        As[akc + 0][arow] = av.x;
        As[akc + 1][arow] = av.y;
        As[akc + 2][arow] = av.z;
        As[akc + 3][arow] = av.w;
        *(float4*)&Bs[brow][bnc] = bv;
        __syncthreads();
#pragma unroll
        for (int kk = 0; kk < 8; kk++) {
            float a[8], bb[8];
            *(float4*)&a[0]  = *(const float4*)&As[kk][i0];
            *(float4*)&a[4]  = *(const float4*)&As[kk][i0 + 4];
            *(float4*)&bb[0] = *(const float4*)&Bs[kk][j0];
            *(float4*)&bb[4] = *(const float4*)&Bs[kk][j0 + 4];
#pragma unroll
            for (int i = 0; i < 8; i++)
#pragma unroll
                for (int j = 0; j < 8; j++) acc[i][j] += a[i] * bb[j];
        }
        __syncthreads();
    }

    float bb[8];
#pragma unroll
    for (int j = 0; j < 8; j++) bb[j] = bias[n0 + j0 + j];

    if (mode == 0) {
#pragma unroll
        for (int i = 0; i < 8; i++) {
            int m = m0 + i0 + i;
            float4 v0, v1;
            v0.x = (acc[i][0] + bb[0]) * scale;
            v0.y = (acc[i][1] + bb[1]) * scale;
            v0.z = (acc[i][2] + bb[2]) * scale;
            v0.w = (acc[i][3] + bb[3]) * scale;
            v1.x = (acc[i][4] + bb[4]) * scale;
            v1.y = (acc[i][5] + bb[5]) * scale;
            v1.z = (acc[i][6] + bb[6]) * scale;
            v1.w = (acc[i][7] + bb[7]) * scale;
            *(float4*)&C[m * N + n0 + j0]     = v0;
            *(float4*)&C[m * N + n0 + j0 + 4] = v1;
        }
    } else {
        // headed layout: [batch, head, seq, hs]
        const int bbatch = m0 / SEQ;             // 128-row tile fully inside one batch
        const int n = n0 + j0;
        const int h = n / HS, d0 = n % HS;       // 8 cols fully inside one head
        const int base = ((bbatch * HEADS + h) * SEQ) * HS;
#pragma unroll
        for (int i = 0; i < 8; i++) {
            int s = m0 + i0 + i - bbatch * SEQ;
            float4 v0, v1;
            v0.x = (acc[i][0] + bb[0]) * scale;
            v0.y = (acc[i][1] + bb[1]) * scale;
            v0.z = (acc[i][2] + bb[2]) * scale;
            v0.w = (acc[i][3] + bb[3]) * scale;
            v1.x = (acc[i][4] + bb[4]) * scale;
            v1.y = (acc[i][5] + bb[5]) * scale;
            v1.z = (acc[i][6] + bb[6]) * scale;
            v1.w = (acc[i][7] + bb[7]) * scale;
            *(float4*)&C[base + s * HS + d0]     = v0;
            *(float4*)&C[base + s * HS + d0 + 4] = v1;
        }
    }
}

// ---------------------------------------------------------------------------
// Flash attention fp32: per (b,h), 64-query tile, loop over 64-key tiles.
// Smem layouts (stride 64, XOR swizzle on high bits keeps stores <=2-way
// conflicted while compute loads remain LDS.128, conflict-free):
//   Qs : offset(d, s) = d*64 + (s ^ (d & 60))   (Q transposed)
//   KPs: as K tile -> offset(d, s) = d*64 + (s ^ (d & 60))
//        as P tile -> offset(k, i) = k*64 + (i ^ (k & 60))  (K dead by then)
//   Vs : offset(s, d) = s*64 + d                 (natural)
// Total smem: 3 * 16 KB = 48 KB exactly.
// ---------------------------------------------------------------------------
__global__ __launch_bounds__(256)
void flash_attn(const float* __restrict__ Q, const float* __restrict__ K,
                const float* __restrict__ V, float* __restrict__ O)
{
    __shared__ float Qs[64 * 64];
    __shared__ float KPs[64 * 64];
    __shared__ float Vs[64 * 64];

    const int tid = threadIdx.x;
    const int qt = blockIdx.x, h = blockIdx.y, b = blockIdx.z;
    const int ty = tid >> 4, tx = tid & 15;
    const int i0 = ty * 4, j0 = tx * 4;

    const float* Qb = Q + ((b * HEADS + h) * SEQ + qt * 64) * HS;
    const float* Kb = K + ((b * HEADS + h) * SEQ) * HS;
    const float* Vb = V + ((b * HEADS + h) * SEQ) * HS;

    // Load Q tile, transposed + swizzled
#pragma unroll
    for (int r = 0; r < 4; r++) {
        int e = tid + r * 256;
        int sl = e >> 4, d0 = (e & 15) * 4;
        int c = sl ^ d0;                       // (d0+q)&60 == d0 for q in 0..3
        float4 v = *(const float4*)&Qb[sl * HS + d0];
        Qs[(d0 + 0) * 64 + c] = v.x;
        Qs[(d0 + 1) * 64 + c] = v.y;
        Qs[(d0 + 2) * 64 + c] = v.z;
        Qs[(d0 + 3) * 64 + c] = v.w;
    }

    float m_i[4] = {-1e30f, -1e30f, -1e30f, -1e30f};
    float l_i[4] = {0.f, 0.f, 0.f, 0.f};
    float o_acc[4][4];
#pragma unroll
    for (int i = 0; i < 4; i++)
#pragma unroll
        for (int j = 0; j < 4; j++) o_acc[i][j] = 0.f;

    for (int t = 0; t < 32; t++) {
        __syncthreads();   // previous tile compute done (and Q load at t=0)
        // Load K tile (transposed+swizzled) and V tile (natural)
#pragma unroll
        for (int r = 0; r < 4; r++) {
            int e = tid + r * 256;
            int sl = e >> 4, d0 = (e & 15) * 4;
            int c = sl ^ d0;
            float4 kv = *(const float4*)&Kb[(t * 64 + sl) * HS + d0];
            KPs[(d0 + 0) * 64 + c] = kv.x;
            KPs[(d0 + 1) * 64 + c] = kv.y;
            KPs[(d0 + 2) * 64 + c] = kv.z;
            KPs[(d0 + 3) * 64 + c] = kv.w;
            float4 vv = *(const float4*)&Vb[(t * 64 + sl) * HS + d0];
            *(float4*)&Vs[sl * 64 + d0] = vv;
        }
        __syncthreads();

        // S = Q @ K^T  (Q pre-scaled by hs^-0.5)
        float acc[4][4];
#pragma unroll
        for (int i = 0; i < 4; i++)
#pragma unroll
            for (int j = 0; j < 4; j++) acc[i][j] = 0.f;
#pragma unroll 8
        for (int k = 0; k < 64; k++) {
            int kh = k & 60;
            float4 a  = *(const float4*)&Qs[k * 64 + (i0 ^ kh)];
            float4 bf = *(const float4*)&KPs[k * 64 + (j0 ^ kh)];
            acc[0][0] += a.x * bf.x; acc[0][1] += a.x * bf.y;
            acc[0][2] += a.x * bf.z; acc[0][3] += a.x * bf.w;
            acc[1][0] += a.y * bf.x; acc[1][1] += a.y * bf.y;
            acc[1][2] += a.y * bf.z; acc[1][3] += a.y * bf.w;
            acc[2][0] += a.z * bf.x; acc[2][1] += a.z * bf.y;
            acc[2][2] += a.z * bf.z; acc[2][3] += a.z * bf.w;
            acc[3][0] += a.w * bf.x; acc[3][1] += a.w * bf.y;
            acc[3][2] += a.w * bf.z; acc[3][3] += a.w * bf.w;
        }

        // Online softmax (row reductions across the 16 tx lanes)
#pragma unroll
        for (int i = 0; i < 4; i++) {
            float mt = fmaxf(fmaxf(acc[i][0], acc[i][1]),
                             fmaxf(acc[i][2], acc[i][3]));
            mt = fmaxf(mt, __shfl_xor_sync(0xffffffffu, mt, 1));
            mt = fmaxf(mt, __shfl_xor_sync(0xffffffffu, mt, 2));
            mt = fmaxf(mt, __shfl_xor_sync(0xffffffffu, mt, 4));
            mt = fmaxf(mt, __shfl_xor_sync(0xffffffffu, mt, 8));
            float mn = fmaxf(m_i[i], mt);
            float corr = __expf(m_i[i] - mn);
            m_i[i] = mn;
            float rs = 0.f;
#pragma unroll
            for (int j = 0; j < 4; j++) {
                acc[i][j] = __expf(acc[i][j] - mn);
                rs += acc[i][j];
            }
            rs += __shfl_xor_sync(0xffffffffu, rs, 1);
            rs += __shfl_xor_sync(0xffffffffu, rs, 2);
            rs += __shfl_xor_sync(0xffffffffu, rs, 4);
            rs += __shfl_xor_sync(0xffffffffu, rs, 8);
            l_i[i] = l_i[i] * corr + rs;
#pragma unroll
            for (int j = 0; j < 4; j++) o_acc[i][j] *= corr;
        }

        __syncthreads();   // all S-GEMM reads of KPs done before P overwrite
        // Store P into KPs  (offset(k,i) = k*64 + (i ^ (k&60)))
#pragma unroll
        for (int j = 0; j < 4; j++) {
            int kk = j0 + j;
            int c = i0 ^ j0;                  // (j0+j)&60 == j0
            float4 pv;
            pv.x = acc[0][j]; pv.y = acc[1][j];
            pv.z = acc[2][j]; pv.w = acc[3][j];
            *(float4*)&KPs[kk * 64 + c] = pv;
        }
        __syncthreads();

        // O += P @ V
#pragma unroll 8
        for (int k = 0; k < 64; k++) {
            int kh = k & 60;
            float4 a  = *(const float4*)&KPs[k * 64 + (i0 ^ kh)];
            float4 bf = *(const float4*)&Vs[k * 64 + j0];
            o_acc[0][0] += a.x * bf.x; o_acc[0][1] += a.x * bf.y;
            o_acc[0][2] += a.x * bf.z; o_acc[0][3] += a.x * bf.w;
            o_acc[1][0] += a.y * bf.x; o_acc[1][1] += a.y * bf.y;
            o_acc[1][2] += a.y * bf.z; o_acc[1][3] += a.y * bf.w;
            o_acc[2][0] += a.z * bf.x; o_acc[2][1] += a.z * bf.y;
            o_acc[2][2] += a.z * bf.z; o_acc[2][3] += a.z * bf.w;
            o_acc[3][0] += a.w * bf.x; o_acc[3][1] += a.w * bf.y;
            o_acc[3][2] += a.w * bf.z; o_acc[3][3] += a.w * bf.w;
        }
    }

    // Epilogue: normalize and write [B, S, D] layout
#pragma unroll
    for (int i = 0; i < 4; i++) {
        float inv = 1.0f / l_i[i];
        float4 v;
        v.x = o_acc[i][0] * inv;
        v.y = o_acc[i][1] * inv;
        v.z = o_acc[i][2] * inv;
        v.w = o_acc[i][3] * inv;
        int s = qt * 64 + i0 + i;
        *(float4*)&O[(b * SEQ + s) * DIM + h * HS + j0] = v;
    }
}

// ---------------------------------------------------------------------------
extern "C" void kernel_launch(void* const* d_in, const int* in_sizes, int n_in,
                              void* d_out, int out_size)
{
    const float* x  = (const float*)d_in[0];
    const float* Wq = (const float*)d_in[1];
    const float* bq = (const float*)d_in[2];
    const float* Wk = (const float*)d_in[3];
    const float* bk = (const float*)d_in[4];
    const float* Wv = (const float*)d_in[5];
    const float* bv = (const float*)d_in[6];
    const float* Wo = (const float*)d_in[7];
    const float* bo = (const float*)d_in[8];
    float* out = (float*)d_out;

    float *Qp, *Kp, *Vp, *Ap;
    cudaGetSymbolAddress((void**)&Qp, g_Q);
    cudaGetSymbolAddress((void**)&Kp, g_K);
    cudaGetSymbolAddress((void**)&Vp, g_V);
    cudaGetSymbolAddress((void**)&Ap, g_A);

    dim3 gridG(DIM / 128, MTOT / 128);   // (6, 64)
    dim3 gridF(SEQ / 64, HEADS, BATCH);  // (32, 12, 4)

    const float qscale = 0.125f;         // hs^-0.5 = 1/8 folded into Q
    sgemm_bias<<<gridG, 256>>>(x,  Wq, bq, Qp, 1, qscale);
    sgemm_bias<<<gridG, 256>>>(x,  Wk, bk, Kp, 1, 1.0f);
    sgemm_bias<<<gridG, 256>>>(x,  Wv, bv, Vp, 1, 1.0f);
    flash_attn<<<gridF, 256>>>(Qp, Kp, Vp, Ap);
    sgemm_bias<<<gridG, 256>>>(Ap, Wo, bo, out, 0, 1.0f);
}

// round 4
// speedup vs baseline: 3.6285x; 3.6285x over previous
#include <cuda_runtime.h>
#include <cstdint>
#include <math.h>

#define BATCH 4
#define SEQ   2048
#define DIM   768
#define HEADS 12
#define HS    64
#define MTOT  (BATCH*SEQ)
#define GK    DIM

// Scratch (allocation-free: __device__ globals)
static __device__ float g_Q[BATCH*HEADS*SEQ*HS];
static __device__ float g_K[BATCH*HEADS*SEQ*HS];
static __device__ float g_V[BATCH*HEADS*SEQ*HS];
static __device__ float g_A[MTOT*DIM];
static __device__ float g_X[MTOT*DIM];      // tf32-rounded x
static __device__ float g_WT[4*DIM*DIM];    // tf32-rounded W^T (N x K row-major)

// ---------------------------------------------------------------------------
// Helpers
// ---------------------------------------------------------------------------
__device__ __forceinline__ uint32_t s2u(const void* p) {
    uint32_t a;
    asm("{ .reg .u64 t; cvta.to.shared.u64 t, %1; cvt.u32.u64 %0, t; }"
        : "=r"(a) : "l"(p));
    return a;
}
__device__ __forceinline__ float tf32rn(float x) {
    uint32_t r;
    asm("cvt.rna.tf32.f32 %0, %1;" : "=r"(r) : "f"(x));
    return __uint_as_float(r);
}
__device__ __forceinline__ float ex2f(float x) {
    float y;
    asm("ex2.approx.ftz.f32 %0, %1;" : "=f"(y) : "f"(x));
    return y;
}
__device__ __forceinline__ void cp16(uint32_t dst, const void* src) {
    asm volatile("cp.async.cg.shared.global [%0], [%1], 16;"
                 :: "r"(dst), "l"(src) : "memory");
}
#define CP_COMMIT asm volatile("cp.async.commit_group;" ::: "memory")
#define CP_WAIT1  asm volatile("cp.async.wait_group 1;" ::: "memory")
#define CP_WAIT0  asm volatile("cp.async.wait_group 0;" ::: "memory")

// D += A * B  (m16n8k8 tf32, A row-major frag, B col-major frag)
__device__ __forceinline__ void mma_tf32(float* d, uint32_t a0, uint32_t a1,
                                         uint32_t a2, uint32_t a3,
                                         uint32_t b0, uint32_t b1) {
    asm volatile(
        "mma.sync.aligned.m16n8k8.row.col.f32.tf32.tf32.f32 "
        "{%0,%1,%2,%3}, {%4,%5,%6,%7}, {%8,%9}, {%0,%1,%2,%3};"
        : "+f"(d[0]), "+f"(d[1]), "+f"(d[2]), "+f"(d[3])
        : "r"(a0), "r"(a1), "r"(a2), "r"(a3), "r"(b0), "r"(b1));
}

// ---------------------------------------------------------------------------
// Prep kernels
// ---------------------------------------------------------------------------
__global__ void round_x_k(const float* __restrict__ x, float* __restrict__ y, int n) {
    int i = (blockIdx.x * blockDim.x + threadIdx.x) * 4;
    if (i < n) {
        float4 v = *(const float4*)&x[i];
        v.x = tf32rn(v.x); v.y = tf32rn(v.y);
        v.z = tf32rn(v.z); v.w = tf32rn(v.w);
        *(float4*)&y[i] = v;
    }
}

__global__ void transpose_w(const float* __restrict__ W0, const float* __restrict__ W1,
                            const float* __restrict__ W2, const float* __restrict__ W3,
                            float* __restrict__ WT) {
    __shared__ float t[32][33];
    const float* W = (blockIdx.z == 0) ? W0 : (blockIdx.z == 1) ? W1
                   : (blockIdx.z == 2) ? W2 : W3;
    float* O = WT + blockIdx.z * DIM * DIM;
    int k0 = blockIdx.y * 32, n0 = blockIdx.x * 32;
    for (int r = threadIdx.y; r < 32; r += 8)
        t[r][threadIdx.x] = W[(k0 + r) * DIM + n0 + threadIdx.x];
    __syncthreads();
    for (int r = threadIdx.y; r < 32; r += 8)
        O[(n0 + r) * DIM + k0 + threadIdx.x] = tf32rn(t[threadIdx.x][r]);
}

// ---------------------------------------------------------------------------
// tf32 warp-MMA GEMM: C = (A[M,K] @ Bt[N,K]^T + bias) * scale
// CTA 128x128, BK=32, 8 warps (4 m x 2 n), warp tile 32x64.
// smem tiles [row][k] stride 36 words -> conflict-free fragment LDS.
// mode 0: plain C[m*DIM+n]   mode 1: headed [B,HEADS,SEQ,HS] + tf32 round
// ---------------------------------------------------------------------------
#define GST (36)          // smem row stride (words)
#define GTILE (128*GST)   // words per tile

__global__ __launch_bounds__(256, 2)
void gemm_tc(const float* __restrict__ A, const float* __restrict__ Bt,
             const float* __restrict__ bias, float* __restrict__ C,
             int mode, float scale)
{
    extern __shared__ float sm[];
    const int tid = threadIdx.x;
    const int wid = tid >> 5, lane = tid & 31;
    const int wm = wid & 3, wn = wid >> 2;
    const int r = lane >> 2, q = lane & 3;
    const int m0 = blockIdx.y * 128, n0 = blockIdx.x * 128;

    const float* AsB[2] = { sm,             sm + 2*GTILE };
    const float* BsB[2] = { sm + GTILE,     sm + 3*GTILE };
    const uint32_t sbase = s2u(sm);

    float acc[2][8][4];
#pragma unroll
    for (int mt = 0; mt < 2; mt++)
#pragma unroll
        for (int nt = 0; nt < 8; nt++)
#pragma unroll
            for (int j = 0; j < 4; j++) acc[mt][nt][j] = 0.f;

    auto load_tiles = [&](int kc, int buf) {
        uint32_t ab = sbase + (uint32_t)buf * 2u * GTILE * 4u;
        uint32_t bb = ab + GTILE * 4u;
#pragma unroll
        for (int i = 0; i < 4; i++) {
            int e = tid + i * 256;
            int row = e >> 3, c4 = e & 7;
            cp16(ab + row * (GST*4) + c4 * 16, A  + (m0 + row) * GK + kc + c4 * 4);
            cp16(bb + row * (GST*4) + c4 * 16, Bt + (n0 + row) * GK + kc + c4 * 4);
        }
    };

    load_tiles(0, 0);
    CP_COMMIT;

    const int NIT = GK / 32;   // 24
    for (int it = 0; it < NIT; it++) {
        if (it + 1 < NIT) { load_tiles((it + 1) * 32, (it + 1) & 1); CP_COMMIT; CP_WAIT1; }
        else              { CP_WAIT0; }
        __syncthreads();
        const float* Ab = AsB[it & 1];
        const float* Bb = BsB[it & 1];
#pragma unroll
        for (int ks = 0; ks < 4; ks++) {
            uint32_t af[2][4];
#pragma unroll
            for (int mt = 0; mt < 2; mt++) {
                int mr = wm * 32 + mt * 16;
                af[mt][0] = __float_as_uint(Ab[(mr + r    ) * GST + ks * 8 + q    ]);
                af[mt][1] = __float_as_uint(Ab[(mr + r + 8) * GST + ks * 8 + q    ]);
                af[mt][2] = __float_as_uint(Ab[(mr + r    ) * GST + ks * 8 + q + 4]);
                af[mt][3] = __float_as_uint(Ab[(mr + r + 8) * GST + ks * 8 + q + 4]);
            }
#pragma unroll
            for (int nt = 0; nt < 8; nt++) {
                uint32_t b0 = __float_as_uint(Bb[(wn * 64 + nt * 8 + r) * GST + ks * 8 + q    ]);
                uint32_t b1 = __float_as_uint(Bb[(wn * 64 + nt * 8 + r) * GST + ks * 8 + q + 4]);
                mma_tf32(acc[0][nt], af[0][0], af[0][1], af[0][2], af[0][3], b0, b1);
                mma_tf32(acc[1][nt], af[1][0], af[1][1], af[1][2], af[1][3], b0, b1);
            }
        }
        __syncthreads();
    }

    // Epilogue
#pragma unroll
    for (int mt = 0; mt < 2; mt++) {
        int row = m0 + wm * 32 + mt * 16 + r;
#pragma unroll
        for (int nt = 0; nt < 8; nt++) {
            int col = n0 + wn * 64 + nt * 8 + 2 * q;
            float b0v = bias[col], b1v = bias[col + 1];
            float v0 = (acc[mt][nt][0] + b0v) * scale;
            float v1 = (acc[mt][nt][1] + b1v) * scale;
            float v2 = (acc[mt][nt][2] + b0v) * scale;
            float v3 = (acc[mt][nt][3] + b1v) * scale;
            if (mode == 0) {
                *(float2*)&C[row * DIM + col]       = make_float2(v0, v1);
                *(float2*)&C[(row + 8) * DIM + col] = make_float2(v2, v3);
            } else {
                int b = row >> 11;
                int h = col >> 6, d = col & 63;
                int s1 = row & 2047, s2 = (row + 8) & 2047;
                float* base = C + ((b * HEADS + h) * SEQ) * HS + d;
                *(float2*)&base[s1 * HS] = make_float2(tf32rn(v0), tf32rn(v1));
                *(float2*)&base[s2 * HS] = make_float2(tf32rn(v2), tf32rn(v3));
            }
        }
    }
}

// ---------------------------------------------------------------------------
// Flash attention, tf32 warp-MMA.
// CTA: 128 q-rows, 8 warps (16 rows each), key tiles of 64, double-buffered
// cp.async K/V. Q fragments persistent in registers (loaded once via smem).
// P round-trips through warp-private smem rows (no CTA-wide hazard).
// Q pre-scaled by hs^-0.5 * log2(e); softmax in exp2 domain.
// smem: Ks[2][64*68], Vs[2][64*72], Ps[128*68]  = 106,496 B
// ---------------------------------------------------------------------------
#define KST 68
#define VST 72
#define PST 68

__global__ __launch_bounds__(256, 2)
void flash_attn(const float* __restrict__ Q, const float* __restrict__ K,
                const float* __restrict__ V, float* __restrict__ O)
{
    extern __shared__ float fs[];
    float* Ks = fs;
    float* Vs = fs + 2 * 64 * KST;
    float* Ps = fs + 2 * 64 * KST + 2 * 64 * VST;

    const int tid = threadIdx.x;
    const int wid = tid >> 5, lane = tid & 31;
    const int r = lane >> 2, q = lane & 3;
    const int mrow = wid * 16;
    const int q0 = blockIdx.x * 128, h = blockIdx.y, b = blockIdx.z;

    const float* Qg = Q + ((b * HEADS + h) * SEQ + q0) * HS;
    const float* Kg = K + ((b * HEADS + h) * SEQ) * HS;
    const float* Vg = V + ((b * HEADS + h) * SEQ) * HS;

    const uint32_t ksaddr = s2u(Ks), vsaddr = s2u(Vs);

    // Stage Q -> Ps region, then read persistent fragments
#pragma unroll
    for (int i = 0; i < 8; i++) {
        int e = tid + i * 256;
        int row = e >> 4, c4 = e & 15;
        float4 v = *(const float4*)&Qg[row * HS + c4 * 4];
        *(float4*)&Ps[row * PST + c4 * 4] = v;
    }
    __syncthreads();
    uint32_t qf[8][4];
#pragma unroll
    for (int ks = 0; ks < 8; ks++) {
        qf[ks][0] = __float_as_uint(Ps[(mrow + r    ) * PST + ks * 8 + q    ]);
        qf[ks][1] = __float_as_uint(Ps[(mrow + r + 8) * PST + ks * 8 + q    ]);
        qf[ks][2] = __float_as_uint(Ps[(mrow + r    ) * PST + ks * 8 + q + 4]);
        qf[ks][3] = __float_as_uint(Ps[(mrow + r + 8) * PST + ks * 8 + q + 4]);
    }

    float m1 = -1e30f, m2 = -1e30f, l1 = 0.f, l2 = 0.f;
    float oacc[8][4];
#pragma unroll
    for (int nt = 0; nt < 8; nt++)
#pragma unroll
        for (int j = 0; j < 4; j++) oacc[nt][j] = 0.f;

    auto load_kv = [&](int t, int buf) {
        uint32_t kb = ksaddr + (uint32_t)buf * 64u * KST * 4u;
        uint32_t vb = vsaddr + (uint32_t)buf * 64u * VST * 4u;
#pragma unroll
        for (int i = 0; i < 4; i++) {
            int e = tid + i * 256;
            int row = e >> 4, c4 = e & 15;
            cp16(kb + row * (KST*4) + c4 * 16, Kg + (t * 64 + row) * HS + c4 * 4);
            cp16(vb + row * (VST*4) + c4 * 16, Vg + (t * 64 + row) * HS + c4 * 4);
        }
    };

    load_kv(0, 0);
    CP_COMMIT;

    const int NT = SEQ / 64;  // 32
    for (int t = 0; t < NT; t++) {
        if (t + 1 < NT) { load_kv(t + 1, (t + 1) & 1); CP_COMMIT; CP_WAIT1; }
        else            { CP_WAIT0; }
        __syncthreads();
        const float* Kb = Ks + (t & 1) * 64 * KST;
        const float* Vb = Vs + (t & 1) * 64 * VST;

        // S = Q @ K^T
        float sacc[8][4];
#pragma unroll
        for (int nt = 0; nt < 8; nt++)
#pragma unroll
            for (int j = 0; j < 4; j++) sacc[nt][j] = 0.f;
#pragma unroll
        for (int ks = 0; ks < 8; ks++) {
#pragma unroll
            for (int nt = 0; nt < 8; nt++) {
                uint32_t b0 = __float_as_uint(Kb[(nt * 8 + r) * KST + ks * 8 + q    ]);
                uint32_t b1 = __float_as_uint(Kb[(nt * 8 + r) * KST + ks * 8 + q + 4]);
                mma_tf32(sacc[nt], qf[ks][0], qf[ks][1], qf[ks][2], qf[ks][3], b0, b1);
            }
        }

        // Online softmax (exp2 domain; rows mrow+r and mrow+r+8)
        float mt1 = -1e30f, mt2 = -1e30f;
#pragma unroll
        for (int nt = 0; nt < 8; nt++) {
            mt1 = fmaxf(mt1, fmaxf(sacc[nt][0], sacc[nt][1]));
            mt2 = fmaxf(mt2, fmaxf(sacc[nt][2], sacc[nt][3]));
        }
        mt1 = fmaxf(mt1, __shfl_xor_sync(0xffffffffu, mt1, 1));
        mt1 = fmaxf(mt1, __shfl_xor_sync(0xffffffffu, mt1, 2));
        mt2 = fmaxf(mt2, __shfl_xor_sync(0xffffffffu, mt2, 1));
        mt2 = fmaxf(mt2, __shfl_xor_sync(0xffffffffu, mt2, 2));
        float mn1 = fmaxf(m1, mt1), mn2 = fmaxf(m2, mt2);
        float c1 = ex2f(m1 - mn1), c2 = ex2f(m2 - mn2);
        m1 = mn1; m2 = mn2;
        float rs1 = 0.f, rs2 = 0.f;
#pragma unroll
        for (int nt = 0; nt < 8; nt++) {
            sacc[nt][0] = ex2f(sacc[nt][0] - mn1); rs1 += sacc[nt][0];
            sacc[nt][1] = ex2f(sacc[nt][1] - mn1); rs1 += sacc[nt][1];
            sacc[nt][2] = ex2f(sacc[nt][2] - mn2); rs2 += sacc[nt][2];
            sacc[nt][3] = ex2f(sacc[nt][3] - mn2); rs2 += sacc[nt][3];
        }
        rs1 += __shfl_xor_sync(0xffffffffu, rs1, 1);
        rs1 += __shfl_xor_sync(0xffffffffu, rs1, 2);
        rs2 += __shfl_xor_sync(0xffffffffu, rs2, 1);
        rs2 += __shfl_xor_sync(0xffffffffu, rs2, 2);
        l1 = l1 * c1 + rs1;
        l2 = l2 * c2 + rs2;
#pragma unroll
        for (int nt = 0; nt < 8; nt++) {
            oacc[nt][0] *= c1; oacc[nt][1] *= c1;
            oacc[nt][2] *= c2; oacc[nt][3] *= c2;
        }

        // P -> warp-private smem rows (tf32-rounded)
        const int pr1 = (mrow + r) * PST, pr2 = (mrow + r + 8) * PST;
#pragma unroll
        for (int nt = 0; nt < 8; nt++) {
            *(float2*)&Ps[pr1 + nt * 8 + 2 * q] =
                make_float2(tf32rn(sacc[nt][0]), tf32rn(sacc[nt][1]));
            *(float2*)&Ps[pr2 + nt * 8 + 2 * q] =
                make_float2(tf32rn(sacc[nt][2]), tf32rn(sacc[nt][3]));
        }
        __syncwarp();

        // O += P @ V
#pragma unroll
        for (int ks = 0; ks < 8; ks++) {
            uint32_t a0 = __float_as_uint(Ps[pr1 + ks * 8 + q    ]);
            uint32_t a1 = __float_as_uint(Ps[pr2 + ks * 8 + q    ]);
            uint32_t a2 = __float_as_uint(Ps[pr1 + ks * 8 + q + 4]);
            uint32_t a3 = __float_as_uint(Ps[pr2 + ks * 8 + q + 4]);
#pragma unroll
            for (int nt = 0; nt < 8; nt++) {
                uint32_t b0 = __float_as_uint(Vb[(ks * 8 + q    ) * VST + nt * 8 + r]);
                uint32_t b1 = __float_as_uint(Vb[(ks * 8 + q + 4) * VST + nt * 8 + r]);
                mma_tf32(oacc[nt], a0, a1, a2, a3, b0, b1);
            }
        }
        __syncthreads();
    }

    // Epilogue: normalize, tf32-round (feeds O-projection), write [B,S,D]
    float i1 = 1.0f / l1, i2 = 1.0f / l2;
    const int row1 = q0 + mrow + r;
#pragma unroll
    for (int nt = 0; nt < 8; nt++) {
        int col = h * HS + nt * 8 + 2 * q;
        *(float2*)&O[(b * SEQ + row1) * DIM + col] =
            make_float2(tf32rn(oacc[nt][0] * i1), tf32rn(oacc[nt][1] * i1));
        *(float2*)&O[(b * SEQ + row1 + 8) * DIM + col] =
            make_float2(tf32rn(oacc[nt][2] * i2), tf32rn(oacc[nt][3] * i2));
    }
}

// ---------------------------------------------------------------------------
extern "C" void kernel_launch(void* const* d_in, const int* in_sizes, int n_in,
                              void* d_out, int out_size)
{
    const float* x  = (const float*)d_in[0];
    const float* Wq = (const float*)d_in[1];
    const float* bq = (const float*)d_in[2];
    const float* Wk = (const float*)d_in[3];
    const float* bk = (const float*)d_in[4];
    const float* Wv = (const float*)d_in[5];
    const float* bv = (const float*)d_in[6];
    const float* Wo = (const float*)d_in[7];
    const float* bo = (const float*)d_in[8];
    float* out = (float*)d_out;

    float *Qp, *Kp, *Vp, *Ap, *Xp, *WTp;
    cudaGetSymbolAddress((void**)&Qp,  g_Q);
    cudaGetSymbolAddress((void**)&Kp,  g_K);
    cudaGetSymbolAddress((void**)&Vp,  g_V);
    cudaGetSymbolAddress((void**)&Ap,  g_A);
    cudaGetSymbolAddress((void**)&Xp,  g_X);
    cudaGetSymbolAddress((void**)&WTp, g_WT);

    const int GEMM_SMEM  = 4 * GTILE * 4;                              // 73,728
    const int FLASH_SMEM = (2*64*KST + 2*64*VST + 128*PST) * 4;        // 106,496
    cudaFuncSetAttribute(gemm_tc,    cudaFuncAttributeMaxDynamicSharedMemorySize, GEMM_SMEM);
    cudaFuncSetAttribute(flash_attn, cudaFuncAttributeMaxDynamicSharedMemorySize, FLASH_SMEM);

    dim3 gridG(DIM / 128, MTOT / 128);    // (6, 64)
    dim3 gridF(SEQ / 128, HEADS, BATCH);  // (16, 12, 4)

    round_x_k<<<(MTOT * DIM / 4 + 255) / 256, 256>>>(x, Xp, MTOT * DIM);
    transpose_w<<<dim3(DIM / 32, DIM / 32, 4), dim3(32, 8)>>>(Wq, Wk, Wv, Wo, WTp);

    // hs^-0.5 * log2(e) folded into Q (softmax runs in exp2 domain)
    const float qscale = 0.125f * 1.44269504088896340736f;
    gemm_tc<<<gridG, 256, GEMM_SMEM>>>(Xp, WTp + 0 * DIM * DIM, bq, Qp, 1, qscale);
    gemm_tc<<<gridG, 256, GEMM_SMEM>>>(Xp, WTp + 1 * DIM * DIM, bk, Kp, 1, 1.0f);
    gemm_tc<<<gridG, 256, GEMM_SMEM>>>(Xp, WTp + 2 * DIM * DIM, bv, Vp, 1, 1.0f);
    flash_attn<<<gridF, 256, FLASH_SMEM>>>(Qp, Kp, Vp, Ap);
    gemm_tc<<<gridG, 256, GEMM_SMEM>>>(Ap, WTp + 3 * DIM * DIM, bo, out, 0, 1.0f);
}

// round 5
// speedup vs baseline: 4.3764x; 1.2061x over previous
#include <cuda_runtime.h>
#include <cstdint>
#include <math.h>

#define BATCH 4
#define SEQ   2048
#define DIM   768
#define HEADS 12
#define HS    64
#define MTOT  (BATCH*SEQ)
#define GK    DIM

// Scratch (allocation-free: __device__ globals)
static __device__ float g_Q[BATCH*HEADS*SEQ*HS];
static __device__ float g_K[BATCH*HEADS*SEQ*HS];
static __device__ float g_V[BATCH*HEADS*SEQ*HS];   // stored [B,H,hs,S] (transposed)
static __device__ float g_A[MTOT*DIM];
static __device__ float g_X[MTOT*DIM];      // tf32-rounded x
static __device__ float g_WT[4*DIM*DIM];    // tf32-rounded W^T (N x K row-major)

// ---------------------------------------------------------------------------
// Helpers
// ---------------------------------------------------------------------------
__device__ __forceinline__ uint32_t s2u(const void* p) {
    uint32_t a;
    asm("{ .reg .u64 t; cvta.to.shared.u64 t, %1; cvt.u32.u64 %0, t; }"
        : "=r"(a) : "l"(p));
    return a;
}
__device__ __forceinline__ float tf32rn(float x) {
    uint32_t r;
    asm("cvt.rna.tf32.f32 %0, %1;" : "=r"(r) : "f"(x));
    return __uint_as_float(r);
}
__device__ __forceinline__ float ex2f(float x) {
    float y;
    asm("ex2.approx.ftz.f32 %0, %1;" : "=f"(y) : "f"(x));
    return y;
}
__device__ __forceinline__ void cp16(uint32_t dst, const void* src) {
    asm volatile("cp.async.cg.shared.global [%0], [%1], 16;"
                 :: "r"(dst), "l"(src) : "memory");
}
#define CP_COMMIT asm volatile("cp.async.commit_group;" ::: "memory")
#define CP_WAIT0  asm volatile("cp.async.wait_group 0;" ::: "memory")

// ldmatrix x4: four 8x8 b16 tiles == 16x8 f32 (A frag) or 8x8 f32 pair (B frags)
__device__ __forceinline__ void ldsm4(uint32_t& r0, uint32_t& r1, uint32_t& r2,
                                      uint32_t& r3, uint32_t a) {
    asm volatile("ldmatrix.sync.aligned.m8n8.x4.shared.b16 {%0,%1,%2,%3}, [%4];"
        : "=r"(r0), "=r"(r1), "=r"(r2), "=r"(r3) : "r"(a));
}

// D += A * B  (m16n8k8 tf32)
__device__ __forceinline__ void mma_tf32(float* d, uint32_t a0, uint32_t a1,
                                         uint32_t a2, uint32_t a3,
                                         uint32_t b0, uint32_t b1) {
    asm volatile(
        "mma.sync.aligned.m16n8k8.row.col.f32.tf32.tf32.f32 "
        "{%0,%1,%2,%3}, {%4,%5,%6,%7}, {%8,%9}, {%0,%1,%2,%3};"
        : "+f"(d[0]), "+f"(d[1]), "+f"(d[2]), "+f"(d[3])
        : "r"(a0), "r"(a1), "r"(a2), "r"(a3), "r"(b0), "r"(b1));
}

// ---------------------------------------------------------------------------
// Prep kernels
// ---------------------------------------------------------------------------
__global__ void round_x_k(const float* __restrict__ x, float* __restrict__ y, int n) {
    int i = (blockIdx.x * blockDim.x + threadIdx.x) * 4;
    if (i < n) {
        float4 v = *(const float4*)&x[i];
        v.x = tf32rn(v.x); v.y = tf32rn(v.y);
        v.z = tf32rn(v.z); v.w = tf32rn(v.w);
        *(float4*)&y[i] = v;
    }
}

__global__ void transpose_w(const float* __restrict__ W0, const float* __restrict__ W1,
                            const float* __restrict__ W2, const float* __restrict__ W3,
                            float* __restrict__ WT) {
    __shared__ float t[32][33];
    const float* W = (blockIdx.z == 0) ? W0 : (blockIdx.z == 1) ? W1
                   : (blockIdx.z == 2) ? W2 : W3;
    float* O = WT + blockIdx.z * DIM * DIM;
    int k0 = blockIdx.y * 32, n0 = blockIdx.x * 32;
    for (int r = threadIdx.y; r < 32; r += 8)
        t[r][threadIdx.x] = W[(k0 + r) * DIM + n0 + threadIdx.x];
    __syncthreads();
    for (int r = threadIdx.y; r < 32; r += 8)
        O[(n0 + r) * DIM + k0 + threadIdx.x] = tf32rn(t[threadIdx.x][r]);
}

// ---------------------------------------------------------------------------
// tf32 warp-MMA GEMM.
//  fused=1: A[8192,768] @ {Wq|Wk|Wv}^T, grid.x=18; which = bx/6 selects output.
//           Q,K headed [B,H,S,hs]; V headed TRANSPOSED [B,H,hs,S]. tf32-rounded.
//  fused=0: plain C0 = A @ Bt^T + bias0 (output projection), grid.x=6.
// CTA 128x128, BK=32, 8 warps (4m x 2n), warp tile 32x64, ldmatrix fragments,
// single __syncthreads per iter, cp.async double buffer.
// ---------------------------------------------------------------------------
#define GSTB   144          // smem row stride bytes (36 words)
#define GTILEB 18432        // 128*144

__global__ __launch_bounds__(256, 2)
void gemm_tc(const float* __restrict__ A, const float* __restrict__ Bt,
             const float* __restrict__ bias0, const float* __restrict__ bias1,
             const float* __restrict__ bias2,
             float* __restrict__ C0, float* __restrict__ C1, float* __restrict__ C2,
             int fused, float qscale)
{
    extern __shared__ float sm[];
    const int tid = threadIdx.x;
    const int wid = tid >> 5, lane = tid & 31;
    const int wm = wid & 3, wn = wid >> 2;
    const int r = lane >> 2, q = lane & 3;
    const int m0 = blockIdx.y * 128;
    const uint32_t sbase = s2u(sm);

    // ldmatrix lane-offsets (bytes, relative to tile base)
    const int lrA  = (lane & 7) + ((lane >> 3) & 1) * 8;   // A-type row
    const int loA  = ((lane >> 4) & 1) * 16;
    const int lrB  = (lane & 7) + ((lane >> 4) & 1) * 8;   // B-type row
    const int loB  = ((lane >> 3) & 1) * 16;
    uint32_t offA[2], offB[4];
#pragma unroll
    for (int mt = 0; mt < 2; mt++)
        offA[mt] = (uint32_t)((wm * 32 + mt * 16 + lrA) * GSTB + loA);
#pragma unroll
    for (int p = 0; p < 4; p++)
        offB[p] = (uint32_t)((wn * 64 + p * 16 + lrB) * GSTB + loB);

    float acc[2][8][4];
#pragma unroll
    for (int mt = 0; mt < 2; mt++)
#pragma unroll
        for (int nt = 0; nt < 8; nt++)
#pragma unroll
            for (int j = 0; j < 4; j++) acc[mt][nt][j] = 0.f;

    const int btrow0 = blockIdx.x * 128;
    auto load_tiles = [&](int kc, int buf) {
        uint32_t ab = sbase + (uint32_t)buf * 2u * GTILEB;
        uint32_t bb = ab + GTILEB;
#pragma unroll
        for (int i = 0; i < 4; i++) {
            int e = tid + i * 256;
            int row = e >> 3, c4 = e & 7;
            cp16(ab + row * GSTB + c4 * 16, A  + (m0 + row) * GK + kc + c4 * 4);
            cp16(bb + row * GSTB + c4 * 16, Bt + (btrow0 + row) * GK + kc + c4 * 4);
        }
    };

    load_tiles(0, 0);
    CP_COMMIT;

    const int NIT = GK / 32;   // 24
    for (int it = 0; it < NIT; it++) {
        CP_WAIT0;
        __syncthreads();
        if (it + 1 < NIT) { load_tiles((it + 1) * 32, (it + 1) & 1); CP_COMMIT; }

        const uint32_t baseA = sbase + (uint32_t)(it & 1) * 2u * GTILEB;
        const uint32_t baseB = baseA + GTILEB;
#pragma unroll
        for (int ks = 0; ks < 4; ks++) {
            uint32_t a[2][4];
            ldsm4(a[0][0], a[0][1], a[0][2], a[0][3], baseA + offA[0] + ks * 32);
            ldsm4(a[1][0], a[1][1], a[1][2], a[1][3], baseA + offA[1] + ks * 32);
#pragma unroll
            for (int p = 0; p < 4; p++) {
                uint32_t b0, b1, b2, b3;
                ldsm4(b0, b1, b2, b3, baseB + offB[p] + ks * 32);
                mma_tf32(acc[0][2*p    ], a[0][0], a[0][1], a[0][2], a[0][3], b0, b1);
                mma_tf32(acc[1][2*p    ], a[1][0], a[1][1], a[1][2], a[1][3], b0, b1);
                mma_tf32(acc[0][2*p + 1], a[0][0], a[0][1], a[0][2], a[0][3], b2, b3);
                mma_tf32(acc[1][2*p + 1], a[1][0], a[1][1], a[1][2], a[1][3], b2, b3);
            }
        }
    }

    // Epilogue
    int which = 0, nloc0 = blockIdx.x * 128;
    const float* bias = bias0;
    float scale = 1.f;
    if (fused) {
        which = blockIdx.x / 6;
        nloc0 = (blockIdx.x % 6) * 128;
        bias  = (which == 0) ? bias0 : (which == 1) ? bias1 : bias2;
        scale = (which == 0) ? qscale : 1.f;
    }

#pragma unroll
    for (int mt = 0; mt < 2; mt++) {
        int row = m0 + wm * 32 + mt * 16 + r;
#pragma unroll
        for (int nt = 0; nt < 8; nt++) {
            int col = nloc0 + wn * 64 + nt * 8 + 2 * q;
            float b0v = bias[col], b1v = bias[col + 1];
            float v0 = (acc[mt][nt][0] + b0v) * scale;
            float v1 = (acc[mt][nt][1] + b1v) * scale;
            float v2 = (acc[mt][nt][2] + b0v) * scale;
            float v3 = (acc[mt][nt][3] + b1v) * scale;
            if (!fused) {
                *(float2*)&C0[row * DIM + col]       = make_float2(v0, v1);
                *(float2*)&C0[(row + 8) * DIM + col] = make_float2(v2, v3);
            } else {
                int b = row >> 11;
                int h = col >> 6, d = col & 63;
                int s1 = row & 2047, s2 = s1 + 8;
                if (which < 2) {
                    float* Cc = which ? C1 : C0;
                    float* base = Cc + ((b * HEADS + h) * SEQ) * HS + d;
                    *(float2*)&base[s1 * HS] = make_float2(tf32rn(v0), tf32rn(v1));
                    *(float2*)&base[s2 * HS] = make_float2(tf32rn(v2), tf32rn(v3));
                } else {
                    // V transposed: [B,H,hs,S]
                    float* base = C2 + ((b * HEADS + h) * HS + d) * SEQ;
                    base[s1]       = tf32rn(v0);
                    base[SEQ + s1] = tf32rn(v1);
                    base[s2]       = tf32rn(v2);
                    base[SEQ + s2] = tf32rn(v3);
                }
            }
        }
    }
}

// ---------------------------------------------------------------------------
// Flash attention, tf32 warp-MMA + ldmatrix fragments.
// CTA: 128 q-rows, 8 warps (16 rows each), 64-key tiles, cp.async dbl buffer,
// single __syncthreads per tile. V in gmem is [B,H,hs,S]; smem Vs is d-major
// so P@V B-fragments come straight from ldmatrix.
// smem: Ks[2][64*68] + Vs[2][64*68] + Ps[128*68] = 104,448 B
// ---------------------------------------------------------------------------
#define FSTB 272            // 68 words
#define FTILEB (64*FSTB)    // 17408

__global__ __launch_bounds__(256, 2)
void flash_attn(const float* __restrict__ Q, const float* __restrict__ K,
                const float* __restrict__ V, float* __restrict__ O)
{
    extern __shared__ float fs[];
    float* Ps = fs + 4 * 64 * 68;

    const int tid = threadIdx.x;
    const int wid = tid >> 5, lane = tid & 31;
    const int r = lane >> 2, q = lane & 3;
    const int mrow = wid * 16;
    const int q0 = blockIdx.x * 128, h = blockIdx.y, b = blockIdx.z;

    const float* Qg = Q + ((b * HEADS + h) * SEQ + q0) * HS;
    const float* Kg = K + ((b * HEADS + h) * SEQ) * HS;
    const float* Vg = V + ((b * HEADS + h) * HS) * SEQ;

    const uint32_t ksaddr = s2u(fs);
    const uint32_t vsaddr = ksaddr + 2 * FTILEB;
    const uint32_t psaddr = vsaddr + 2 * FTILEB;

    // ldmatrix lane-offsets
    const int lrA = (lane & 7) + ((lane >> 3) & 1) * 8;
    const int loA = ((lane >> 4) & 1) * 16;
    const int lrB = (lane & 7) + ((lane >> 4) & 1) * 8;
    const int loB = ((lane >> 3) & 1) * 16;
    const uint32_t offP = (uint32_t)((mrow + lrA) * FSTB + loA);
    uint32_t offBf[4];
#pragma unroll
    for (int p = 0; p < 4; p++)
        offBf[p] = (uint32_t)((p * 16 + lrB) * FSTB + loB);

    auto load_kv = [&](int t, int buf) {
        uint32_t kb = ksaddr + (uint32_t)buf * FTILEB;
        uint32_t vb = vsaddr + (uint32_t)buf * FTILEB;
#pragma unroll
        for (int i = 0; i < 4; i++) {
            int e = tid + i * 256;
            int row = e >> 4, c4 = e & 15;
            cp16(kb + row * FSTB + c4 * 16, Kg + (t * 64 + row) * HS + c4 * 4);
            cp16(vb + row * FSTB + c4 * 16, Vg + row * SEQ + t * 64 + c4 * 4);
        }
    };

    load_kv(0, 0);
    CP_COMMIT;

    // Stage Q -> Ps, read persistent A-fragments via ldmatrix
#pragma unroll
    for (int i = 0; i < 8; i++) {
        int e = tid + i * 256;
        int row = e >> 4, c4 = e & 15;
        float4 v = *(const float4*)&Qg[row * HS + c4 * 4];
        *(float4*)&Ps[row * 68 + c4 * 4] = v;
    }
    __syncthreads();
    uint32_t qf[8][4];
#pragma unroll
    for (int ks = 0; ks < 8; ks++)
        ldsm4(qf[ks][0], qf[ks][1], qf[ks][2], qf[ks][3], psaddr + offP + ks * 32);

    float m1 = -1e30f, m2 = -1e30f, l1 = 0.f, l2 = 0.f;
    float oacc[8][4];
#pragma unroll
    for (int nt = 0; nt < 8; nt++)
#pragma unroll
        for (int j = 0; j < 4; j++) oacc[nt][j] = 0.f;

    const int NT = SEQ / 64;  // 32
    for (int t = 0; t < NT; t++) {
        CP_WAIT0;
        __syncthreads();
        if (t + 1 < NT) { load_kv(t + 1, (t + 1) & 1); CP_COMMIT; }

        const uint32_t kb = ksaddr + (uint32_t)(t & 1) * FTILEB;
        const uint32_t vb = vsaddr + (uint32_t)(t & 1) * FTILEB;

        // S = Q @ K^T
        float sacc[8][4];
#pragma unroll
        for (int nt = 0; nt < 8; nt++)
#pragma unroll
            for (int j = 0; j < 4; j++) sacc[nt][j] = 0.f;
#pragma unroll
        for (int ks = 0; ks < 8; ks++) {
#pragma unroll
            for (int p = 0; p < 4; p++) {
                uint32_t b0, b1, b2, b3;
                ldsm4(b0, b1, b2, b3, kb + offBf[p] + ks * 32);
                mma_tf32(sacc[2*p    ], qf[ks][0], qf[ks][1], qf[ks][2], qf[ks][3], b0, b1);
                mma_tf32(sacc[2*p + 1], qf[ks][0], qf[ks][1], qf[ks][2], qf[ks][3], b2, b3);
            }
        }

        // Online softmax (exp2 domain; rows mrow+r and mrow+r+8)
        float mt1 = -1e30f, mt2 = -1e30f;
#pragma unroll
        for (int nt = 0; nt < 8; nt++) {
            mt1 = fmaxf(mt1, fmaxf(sacc[nt][0], sacc[nt][1]));
            mt2 = fmaxf(mt2, fmaxf(sacc[nt][2], sacc[nt][3]));
        }
        mt1 = fmaxf(mt1, __shfl_xor_sync(0xffffffffu, mt1, 1));
        mt1 = fmaxf(mt1, __shfl_xor_sync(0xffffffffu, mt1, 2));
        mt2 = fmaxf(mt2, __shfl_xor_sync(0xffffffffu, mt2, 1));
        mt2 = fmaxf(mt2, __shfl_xor_sync(0xffffffffu, mt2, 2));
        float mn1 = fmaxf(m1, mt1), mn2 = fmaxf(m2, mt2);
        float c1 = ex2f(m1 - mn1), c2 = ex2f(m2 - mn2);
        m1 = mn1; m2 = mn2;
        float rs1 = 0.f, rs2 = 0.f;
#pragma unroll
        for (int nt = 0; nt < 8; nt++) {
            sacc[nt][0] = ex2f(sacc[nt][0] - mn1); rs1 += sacc[nt][0];
            sacc[nt][1] = ex2f(sacc[nt][1] - mn1); rs1 += sacc[nt][1];
            sacc[nt][2] = ex2f(sacc[nt][2] - mn2); rs2 += sacc[nt][2];
            sacc[nt][3] = ex2f(sacc[nt][3] - mn2); rs2 += sacc[nt][3];
        }
        rs1 += __shfl_xor_sync(0xffffffffu, rs1, 1);
        rs1 += __shfl_xor_sync(0xffffffffu, rs1, 2);
        rs2 += __shfl_xor_sync(0xffffffffu, rs2, 1);
        rs2 += __shfl_xor_sync(0xffffffffu, rs2, 2);
        l1 = l1 * c1 + rs1;
        l2 = l2 * c2 + rs2;
#pragma unroll
        for (int nt = 0; nt < 8; nt++) {
            oacc[nt][0] *= c1; oacc[nt][1] *= c1;
            oacc[nt][2] *= c2; oacc[nt][3] *= c2;
        }

        // P -> warp-private smem rows (tf32-rounded)
        const int pr1 = (mrow + r) * 68, pr2 = (mrow + r + 8) * 68;
#pragma unroll
        for (int nt = 0; nt < 8; nt++) {
            *(float2*)&Ps[pr1 + nt * 8 + 2 * q] =
                make_float2(tf32rn(sacc[nt][0]), tf32rn(sacc[nt][1]));
            *(float2*)&Ps[pr2 + nt * 8 + 2 * q] =
                make_float2(tf32rn(sacc[nt][2]), tf32rn(sacc[nt][3]));
        }
        __syncwarp();

        // O += P @ V   (V smem is d-major: B-frags direct from ldmatrix)
#pragma unroll
        for (int ks = 0; ks < 8; ks++) {
            uint32_t pa0, pa1, pa2, pa3;
            ldsm4(pa0, pa1, pa2, pa3, psaddr + offP + ks * 32);
#pragma unroll
            for (int p = 0; p < 4; p++) {
                uint32_t b0, b1, b2, b3;
                ldsm4(b0, b1, b2, b3, vb + offBf[p] + ks * 32);
                mma_tf32(oacc[2*p    ], pa0, pa1, pa2, pa3, b0, b1);
                mma_tf32(oacc[2*p + 1], pa0, pa1, pa2, pa3, b2, b3);
            }
        }
    }

    // Epilogue: normalize, tf32-round (feeds O-projection), write [B,S,D]
    float i1 = 1.0f / l1, i2 = 1.0f / l2;
    const int row1 = q0 + mrow + r;
#pragma unroll
    for (int nt = 0; nt < 8; nt++) {
        int col = h * HS + nt * 8 + 2 * q;
        *(float2*)&O[(b * SEQ + row1) * DIM + col] =
            make_float2(tf32rn(oacc[nt][0] * i1), tf32rn(oacc[nt][1] * i1));
        *(float2*)&O[(b * SEQ + row1 + 8) * DIM + col] =
            make_float2(tf32rn(oacc[nt][2] * i2), tf32rn(oacc[nt][3] * i2));
    }
}

// ---------------------------------------------------------------------------
extern "C" void kernel_launch(void* const* d_in, const int* in_sizes, int n_in,
                              void* d_out, int out_size)
{
    const float* x  = (const float*)d_in[0];
    const float* Wq = (const float*)d_in[1];
    const float* bq = (const float*)d_in[2];
    const float* Wk = (const float*)d_in[3];
    const float* bk = (const float*)d_in[4];
    const float* Wv = (const float*)d_in[5];
    const float* bv = (const float*)d_in[6];
    const float* Wo = (const float*)d_in[7];
    const float* bo = (const float*)d_in[8];
    float* out = (float*)d_out;

    float *Qp, *Kp, *Vp, *Ap, *Xp, *WTp;
    cudaGetSymbolAddress((void**)&Qp,  g_Q);
    cudaGetSymbolAddress((void**)&Kp,  g_K);
    cudaGetSymbolAddress((void**)&Vp,  g_V);
    cudaGetSymbolAddress((void**)&Ap,  g_A);
    cudaGetSymbolAddress((void**)&Xp,  g_X);
    cudaGetSymbolAddress((void**)&WTp, g_WT);

    const int GEMM_SMEM  = 4 * GTILEB;            // 73,728
    const int FLASH_SMEM = (4*64*68 + 128*68)*4;  // 104,448
    cudaFuncSetAttribute(gemm_tc,    cudaFuncAttributeMaxDynamicSharedMemorySize, GEMM_SMEM);
    cudaFuncSetAttribute(flash_attn, cudaFuncAttributeMaxDynamicSharedMemorySize, FLASH_SMEM);

    round_x_k<<<(MTOT * DIM / 4 + 255) / 256, 256>>>(x, Xp, MTOT * DIM);
    transpose_w<<<dim3(DIM / 32, DIM / 32, 4), dim3(32, 8)>>>(Wq, Wk, Wv, Wo, WTp);

    // hs^-0.5 * log2(e) folded into Q (softmax runs in exp2 domain)
    const float qscale = 0.125f * 1.44269504088896340736f;

    // Fused Q/K/V projection: grid.x spans 3*768 cols
    dim3 gridQKV(3 * DIM / 128, MTOT / 128);   // (18, 64)
    gemm_tc<<<gridQKV, 256, GEMM_SMEM>>>(Xp, WTp, bq, bk, bv, Qp, Kp, Vp, 1, qscale);

    dim3 gridF(SEQ / 128, HEADS, BATCH);       // (16, 12, 4)
    flash_attn<<<gridF, 256, FLASH_SMEM>>>(Qp, Kp, Vp, Ap);

    dim3 gridO(DIM / 128, MTOT / 128);         // (6, 64)
    gemm_tc<<<gridO, 256, GEMM_SMEM>>>(Ap, WTp + 3 * DIM * DIM, bo, bo, bo,
                                       out, out, out, 0, 1.0f);
}

// round 6
// speedup vs baseline: 4.5608x; 1.0421x over previous
#include <cuda_runtime.h>
#include <cstdint>
#include <math.h>

#define BATCH 4
#define SEQ   2048
#define DIM   768
#define HEADS 12
#define HS    64
#define MTOT  (BATCH*SEQ)
#define GK    DIM

// Scratch (allocation-free: __device__ globals)
static __device__ float g_Q[BATCH*HEADS*SEQ*HS];
static __device__ float g_K[BATCH*HEADS*SEQ*HS];
static __device__ float g_V[BATCH*HEADS*SEQ*HS];   // stored [B,H,hs,S] (transposed)
static __device__ float g_A[MTOT*DIM];
static __device__ float g_X[MTOT*DIM];      // tf32-rounded x
static __device__ float g_WT[4*DIM*DIM];    // tf32-rounded W^T (N x K row-major)

// ---------------------------------------------------------------------------
// Helpers
// ---------------------------------------------------------------------------
__device__ __forceinline__ uint32_t s2u(const void* p) {
    uint32_t a;
    asm("{ .reg .u64 t; cvta.to.shared.u64 t, %1; cvt.u32.u64 %0, t; }"
        : "=r"(a) : "l"(p));
    return a;
}
__device__ __forceinline__ float tf32rn(float x) {
    uint32_t r;
    asm("cvt.rna.tf32.f32 %0, %1;" : "=r"(r) : "f"(x));
    return __uint_as_float(r);
}
__device__ __forceinline__ float ex2f(float x) {
    float y;
    asm("ex2.approx.ftz.f32 %0, %1;" : "=f"(y) : "f"(x));
    return y;
}
__device__ __forceinline__ void cp16(uint32_t dst, const void* src) {
    asm volatile("cp.async.cg.shared.global [%0], [%1], 16;"
                 :: "r"(dst), "l"(src) : "memory");
}
#define CP_COMMIT asm volatile("cp.async.commit_group;" ::: "memory")
#define CP_WAIT0  asm volatile("cp.async.wait_group 0;" ::: "memory")

// ldmatrix x4: four 8x8 b16 tiles == 16x8 f32 (A frag) or 8x8 f32 pair (B frags)
__device__ __forceinline__ void ldsm4(uint32_t& r0, uint32_t& r1, uint32_t& r2,
                                      uint32_t& r3, uint32_t a) {
    asm volatile("ldmatrix.sync.aligned.m8n8.x4.shared.b16 {%0,%1,%2,%3}, [%4];"
        : "=r"(r0), "=r"(r1), "=r"(r2), "=r"(r3) : "r"(a));
}

// D += A * B  (m16n8k8 tf32)
__device__ __forceinline__ void mma_tf32(float* d, uint32_t a0, uint32_t a1,
                                         uint32_t a2, uint32_t a3,
                                         uint32_t b0, uint32_t b1) {
    asm volatile(
        "mma.sync.aligned.m16n8k8.row.col.f32.tf32.tf32.f32 "
        "{%0,%1,%2,%3}, {%4,%5,%6,%7}, {%8,%9}, {%0,%1,%2,%3};"
        : "+f"(d[0]), "+f"(d[1]), "+f"(d[2]), "+f"(d[3])
        : "r"(a0), "r"(a1), "r"(a2), "r"(a3), "r"(b0), "r"(b1));
}

// ---------------------------------------------------------------------------
// Prep kernels
// ---------------------------------------------------------------------------
__global__ void round_x_k(const float* __restrict__ x, float* __restrict__ y, int n) {
    int i = (blockIdx.x * blockDim.x + threadIdx.x) * 4;
    if (i < n) {
        float4 v = *(const float4*)&x[i];
        v.x = tf32rn(v.x); v.y = tf32rn(v.y);
        v.z = tf32rn(v.z); v.w = tf32rn(v.w);
        *(float4*)&y[i] = v;
    }
}

__global__ void transpose_w(const float* __restrict__ W0, const float* __restrict__ W1,
                            const float* __restrict__ W2, const float* __restrict__ W3,
                            float* __restrict__ WT) {
    __shared__ float t[32][33];
    const float* W = (blockIdx.z == 0) ? W0 : (blockIdx.z == 1) ? W1
                   : (blockIdx.z == 2) ? W2 : W3;
    float* O = WT + blockIdx.z * DIM * DIM;
    int k0 = blockIdx.y * 32, n0 = blockIdx.x * 32;
    for (int r = threadIdx.y; r < 32; r += 8)
        t[r][threadIdx.x] = W[(k0 + r) * DIM + n0 + threadIdx.x];
    __syncthreads();
    for (int r = threadIdx.y; r < 32; r += 8)
        O[(n0 + r) * DIM + k0 + threadIdx.x] = tf32rn(t[threadIdx.x][r]);
}

// ---------------------------------------------------------------------------
// tf32 warp-MMA GEMM (unchanged from R5).
//  fused=1: A[8192,768] @ {Wq|Wk|Wv}^T, grid.x=18; which = bx/6 selects output.
//           Q,K headed [B,H,S,hs]; V headed TRANSPOSED [B,H,hs,S]. tf32-rounded.
//  fused=0: plain C0 = A @ Bt^T + bias0 (output projection), grid.x=6.
// ---------------------------------------------------------------------------
#define GSTB   144          // smem row stride bytes (36 words)
#define GTILEB 18432        // 128*144

__global__ __launch_bounds__(256, 2)
void gemm_tc(const float* __restrict__ A, const float* __restrict__ Bt,
             const float* __restrict__ bias0, const float* __restrict__ bias1,
             const float* __restrict__ bias2,
             float* __restrict__ C0, float* __restrict__ C1, float* __restrict__ C2,
             int fused, float qscale)
{
    extern __shared__ float sm[];
    const int tid = threadIdx.x;
    const int wid = tid >> 5, lane = tid & 31;
    const int wm = wid & 3, wn = wid >> 2;
    const int r = lane >> 2, q = lane & 3;
    const int m0 = blockIdx.y * 128;
    const uint32_t sbase = s2u(sm);

    const int lrA  = (lane & 7) + ((lane >> 3) & 1) * 8;
    const int loA  = ((lane >> 4) & 1) * 16;
    const int lrB  = (lane & 7) + ((lane >> 4) & 1) * 8;
    const int loB  = ((lane >> 3) & 1) * 16;
    uint32_t offA[2], offB[4];
#pragma unroll
    for (int mt = 0; mt < 2; mt++)
        offA[mt] = (uint32_t)((wm * 32 + mt * 16 + lrA) * GSTB + loA);
#pragma unroll
    for (int p = 0; p < 4; p++)
        offB[p] = (uint32_t)((wn * 64 + p * 16 + lrB) * GSTB + loB);

    float acc[2][8][4];
#pragma unroll
    for (int mt = 0; mt < 2; mt++)
#pragma unroll
        for (int nt = 0; nt < 8; nt++)
#pragma unroll
            for (int j = 0; j < 4; j++) acc[mt][nt][j] = 0.f;

    const int btrow0 = blockIdx.x * 128;
    auto load_tiles = [&](int kc, int buf) {
        uint32_t ab = sbase + (uint32_t)buf * 2u * GTILEB;
        uint32_t bb = ab + GTILEB;
#pragma unroll
        for (int i = 0; i < 4; i++) {
            int e = tid + i * 256;
            int row = e >> 3, c4 = e & 7;
            cp16(ab + row * GSTB + c4 * 16, A  + (m0 + row) * GK + kc + c4 * 4);
            cp16(bb + row * GSTB + c4 * 16, Bt + (btrow0 + row) * GK + kc + c4 * 4);
        }
    };

    load_tiles(0, 0);
    CP_COMMIT;

    const int NIT = GK / 32;   // 24
    for (int it = 0; it < NIT; it++) {
        CP_WAIT0;
        __syncthreads();
        if (it + 1 < NIT) { load_tiles((it + 1) * 32, (it + 1) & 1); CP_COMMIT; }

        const uint32_t baseA = sbase + (uint32_t)(it & 1) * 2u * GTILEB;
        const uint32_t baseB = baseA + GTILEB;
#pragma unroll
        for (int ks = 0; ks < 4; ks++) {
            uint32_t a[2][4];
            ldsm4(a[0][0], a[0][1], a[0][2], a[0][3], baseA + offA[0] + ks * 32);
            ldsm4(a[1][0], a[1][1], a[1][2], a[1][3], baseA + offA[1] + ks * 32);
#pragma unroll
            for (int p = 0; p < 4; p++) {
                uint32_t b0, b1, b2, b3;
                ldsm4(b0, b1, b2, b3, baseB + offB[p] + ks * 32);
                mma_tf32(acc[0][2*p    ], a[0][0], a[0][1], a[0][2], a[0][3], b0, b1);
                mma_tf32(acc[1][2*p    ], a[1][0], a[1][1], a[1][2], a[1][3], b0, b1);
                mma_tf32(acc[0][2*p + 1], a[0][0], a[0][1], a[0][2], a[0][3], b2, b3);
                mma_tf32(acc[1][2*p + 1], a[1][0], a[1][1], a[1][2], a[1][3], b2, b3);
            }
        }
    }

    int which = 0, nloc0 = blockIdx.x * 128;
    const float* bias = bias0;
    float scale = 1.f;
    if (fused) {
        which = blockIdx.x / 6;
        nloc0 = (blockIdx.x % 6) * 128;
        bias  = (which == 0) ? bias0 : (which == 1) ? bias1 : bias2;
        scale = (which == 0) ? qscale : 1.f;
    }

#pragma unroll
    for (int mt = 0; mt < 2; mt++) {
        int row = m0 + wm * 32 + mt * 16 + r;
#pragma unroll
        for (int nt = 0; nt < 8; nt++) {
            int col = nloc0 + wn * 64 + nt * 8 + 2 * q;
            float b0v = bias[col], b1v = bias[col + 1];
            float v0 = (acc[mt][nt][0] + b0v) * scale;
            float v1 = (acc[mt][nt][1] + b1v) * scale;
            float v2 = (acc[mt][nt][2] + b0v) * scale;
            float v3 = (acc[mt][nt][3] + b1v) * scale;
            if (!fused) {
                *(float2*)&C0[row * DIM + col]       = make_float2(v0, v1);
                *(float2*)&C0[(row + 8) * DIM + col] = make_float2(v2, v3);
            } else {
                int b = row >> 11;
                int h = col >> 6, d = col & 63;
                int s1 = row & 2047, s2 = s1 + 8;
                if (which < 2) {
                    float* Cc = which ? C1 : C0;
                    float* base = Cc + ((b * HEADS + h) * SEQ) * HS + d;
                    *(float2*)&base[s1 * HS] = make_float2(tf32rn(v0), tf32rn(v1));
                    *(float2*)&base[s2 * HS] = make_float2(tf32rn(v2), tf32rn(v3));
                } else {
                    float* base = C2 + ((b * HEADS + h) * HS + d) * SEQ;
                    base[s1]       = tf32rn(v0);
                    base[SEQ + s1] = tf32rn(v1);
                    base[s2]       = tf32rn(v2);
                    base[SEQ + s2] = tf32rn(v3);
                }
            }
        }
    }
}

// ---------------------------------------------------------------------------
// Flash attention, tf32 warp-MMA, 4 warps x 32 q-rows (2 M-frags/warp):
// every K/V B-fragment is amortized over 2x MMAs -> ~40% less smem traffic.
// CTA: 128 q-rows, 128 threads, 64-key tiles, cp.async dbl buffer.
// V gmem is [B,H,hs,S]; smem Vs is d-major. Q persistent in registers.
// smem: Ks[2][64*68] + Vs[2][64*68] + Ps[128*68] = 104,448 B
// ---------------------------------------------------------------------------
#define FSTB 272            // 68 words
#define FTILEB (64*FSTB)    // 17408

__global__ __launch_bounds__(128)
void flash_attn(const float* __restrict__ Q, const float* __restrict__ K,
                const float* __restrict__ V, float* __restrict__ O)
{
    extern __shared__ float fs[];
    float* Ps = fs + 4 * 64 * 68;

    const int tid = threadIdx.x;
    const int wid = tid >> 5, lane = tid & 31;
    const int r = lane >> 2, q = lane & 3;
    const int mrow = wid * 32;
    const int q0 = blockIdx.x * 128, h = blockIdx.y, b = blockIdx.z;

    const float* Qg = Q + ((b * HEADS + h) * SEQ + q0) * HS;
    const float* Kg = K + ((b * HEADS + h) * SEQ) * HS;
    const float* Vg = V + ((b * HEADS + h) * HS) * SEQ;

    const uint32_t ksaddr = s2u(fs);
    const uint32_t vsaddr = ksaddr + 2 * FTILEB;
    const uint32_t psaddr = vsaddr + 2 * FTILEB;

    // ldmatrix lane-offsets
    const int lrA = (lane & 7) + ((lane >> 3) & 1) * 8;
    const int loA = ((lane >> 4) & 1) * 16;
    const int lrB = (lane & 7) + ((lane >> 4) & 1) * 8;
    const int loB = ((lane >> 3) & 1) * 16;
    uint32_t offPA[2];
#pragma unroll
    for (int mt = 0; mt < 2; mt++)
        offPA[mt] = (uint32_t)((mrow + mt * 16 + lrA) * FSTB + loA);
    uint32_t offBf[4];
#pragma unroll
    for (int p = 0; p < 4; p++)
        offBf[p] = (uint32_t)((p * 16 + lrB) * FSTB + loB);

    auto load_kv = [&](int t, int buf) {
        uint32_t kb = ksaddr + (uint32_t)buf * FTILEB;
        uint32_t vb = vsaddr + (uint32_t)buf * FTILEB;
#pragma unroll
        for (int i = 0; i < 8; i++) {
            int e = tid + i * 128;
            int row = e >> 4, c4 = e & 15;
            cp16(kb + row * FSTB + c4 * 16, Kg + (t * 64 + row) * HS + c4 * 4);
            cp16(vb + row * FSTB + c4 * 16, Vg + row * SEQ + t * 64 + c4 * 4);
        }
    };

    load_kv(0, 0);
    CP_COMMIT;

    // Stage Q -> Ps, read persistent A-fragments via ldmatrix (2 M-frags x 8 ks)
#pragma unroll
    for (int i = 0; i < 16; i++) {
        int e = tid + i * 128;
        int row = e >> 4, c4 = e & 15;
        float4 v = *(const float4*)&Qg[row * HS + c4 * 4];
        *(float4*)&Ps[row * 68 + c4 * 4] = v;
    }
    __syncthreads();
    uint32_t qf[2][8][4];
#pragma unroll
    for (int mt = 0; mt < 2; mt++)
#pragma unroll
        for (int ks = 0; ks < 8; ks++)
            ldsm4(qf[mt][ks][0], qf[mt][ks][1], qf[mt][ks][2], qf[mt][ks][3],
                  psaddr + offPA[mt] + ks * 32);

    float mx[2][2], ls[2][2];
#pragma unroll
    for (int mt = 0; mt < 2; mt++) { mx[mt][0] = mx[mt][1] = -1e30f; ls[mt][0] = ls[mt][1] = 0.f; }
    float oacc[2][8][4];
#pragma unroll
    for (int mt = 0; mt < 2; mt++)
#pragma unroll
        for (int nt = 0; nt < 8; nt++)
#pragma unroll
            for (int j = 0; j < 4; j++) oacc[mt][nt][j] = 0.f;

    const int NT = SEQ / 64;  // 32
    for (int t = 0; t < NT; t++) {
        CP_WAIT0;
        __syncthreads();
        if (t + 1 < NT) { load_kv(t + 1, (t + 1) & 1); CP_COMMIT; }

        const uint32_t kb = ksaddr + (uint32_t)(t & 1) * FTILEB;
        const uint32_t vb = vsaddr + (uint32_t)(t & 1) * FTILEB;

        // S = Q @ K^T  (each B-frag feeds both M-frags)
        float sacc[2][8][4];
#pragma unroll
        for (int mt = 0; mt < 2; mt++)
#pragma unroll
            for (int nt = 0; nt < 8; nt++)
#pragma unroll
                for (int j = 0; j < 4; j++) sacc[mt][nt][j] = 0.f;
#pragma unroll
        for (int ks = 0; ks < 8; ks++) {
#pragma unroll
            for (int p = 0; p < 4; p++) {
                uint32_t b0, b1, b2, b3;
                ldsm4(b0, b1, b2, b3, kb + offBf[p] + ks * 32);
                mma_tf32(sacc[0][2*p    ], qf[0][ks][0], qf[0][ks][1], qf[0][ks][2], qf[0][ks][3], b0, b1);
                mma_tf32(sacc[1][2*p    ], qf[1][ks][0], qf[1][ks][1], qf[1][ks][2], qf[1][ks][3], b0, b1);
                mma_tf32(sacc[0][2*p + 1], qf[0][ks][0], qf[0][ks][1], qf[0][ks][2], qf[0][ks][3], b2, b3);
                mma_tf32(sacc[1][2*p + 1], qf[1][ks][0], qf[1][ks][1], qf[1][ks][2], qf[1][ks][3], b2, b3);
            }
        }

        // Online softmax per M-frag (rows mrow+mt*16+r and +8), exp2 domain
#pragma unroll
        for (int mt = 0; mt < 2; mt++) {
            float mt1 = -1e30f, mt2 = -1e30f;
#pragma unroll
            for (int nt = 0; nt < 8; nt++) {
                mt1 = fmaxf(mt1, fmaxf(sacc[mt][nt][0], sacc[mt][nt][1]));
                mt2 = fmaxf(mt2, fmaxf(sacc[mt][nt][2], sacc[mt][nt][3]));
            }
            mt1 = fmaxf(mt1, __shfl_xor_sync(0xffffffffu, mt1, 1));
            mt1 = fmaxf(mt1, __shfl_xor_sync(0xffffffffu, mt1, 2));
            mt2 = fmaxf(mt2, __shfl_xor_sync(0xffffffffu, mt2, 1));
            mt2 = fmaxf(mt2, __shfl_xor_sync(0xffffffffu, mt2, 2));
            float mn1 = fmaxf(mx[mt][0], mt1), mn2 = fmaxf(mx[mt][1], mt2);
            float c1 = ex2f(mx[mt][0] - mn1), c2 = ex2f(mx[mt][1] - mn2);
            mx[mt][0] = mn1; mx[mt][1] = mn2;
            float rs1 = 0.f, rs2 = 0.f;
#pragma unroll
            for (int nt = 0; nt < 8; nt++) {
                sacc[mt][nt][0] = ex2f(sacc[mt][nt][0] - mn1); rs1 += sacc[mt][nt][0];
                sacc[mt][nt][1] = ex2f(sacc[mt][nt][1] - mn1); rs1 += sacc[mt][nt][1];
                sacc[mt][nt][2] = ex2f(sacc[mt][nt][2] - mn2); rs2 += sacc[mt][nt][2];
                sacc[mt][nt][3] = ex2f(sacc[mt][nt][3] - mn2); rs2 += sacc[mt][nt][3];
            }
            rs1 += __shfl_xor_sync(0xffffffffu, rs1, 1);
            rs1 += __shfl_xor_sync(0xffffffffu, rs1, 2);
            rs2 += __shfl_xor_sync(0xffffffffu, rs2, 1);
            rs2 += __shfl_xor_sync(0xffffffffu, rs2, 2);
            ls[mt][0] = ls[mt][0] * c1 + rs1;
            ls[mt][1] = ls[mt][1] * c2 + rs2;
#pragma unroll
            for (int nt = 0; nt < 8; nt++) {
                oacc[mt][nt][0] *= c1; oacc[mt][nt][1] *= c1;
                oacc[mt][nt][2] *= c2; oacc[mt][nt][3] *= c2;
            }

            // P -> warp-private smem rows (tf32-rounded)
            const int pr1 = (mrow + mt * 16 + r) * 68, pr2 = pr1 + 8 * 68;
#pragma unroll
            for (int nt = 0; nt < 8; nt++) {
                *(float2*)&Ps[pr1 + nt * 8 + 2 * q] =
                    make_float2(tf32rn(sacc[mt][nt][0]), tf32rn(sacc[mt][nt][1]));
                *(float2*)&Ps[pr2 + nt * 8 + 2 * q] =
                    make_float2(tf32rn(sacc[mt][nt][2]), tf32rn(sacc[mt][nt][3]));
            }
        }
        __syncwarp();

        // O += P @ V   (V smem d-major; each V B-frag feeds both M-frags)
#pragma unroll
        for (int ks = 0; ks < 8; ks++) {
            uint32_t pa[2][4];
            ldsm4(pa[0][0], pa[0][1], pa[0][2], pa[0][3], psaddr + offPA[0] + ks * 32);
            ldsm4(pa[1][0], pa[1][1], pa[1][2], pa[1][3], psaddr + offPA[1] + ks * 32);
#pragma unroll
            for (int p = 0; p < 4; p++) {
                uint32_t b0, b1, b2, b3;
                ldsm4(b0, b1, b2, b3, vb + offBf[p] + ks * 32);
                mma_tf32(oacc[0][2*p    ], pa[0][0], pa[0][1], pa[0][2], pa[0][3], b0, b1);
                mma_tf32(oacc[1][2*p    ], pa[1][0], pa[1][1], pa[1][2], pa[1][3], b0, b1);
                mma_tf32(oacc[0][2*p + 1], pa[0][0], pa[0][1], pa[0][2], pa[0][3], b2, b3);
                mma_tf32(oacc[1][2*p + 1], pa[1][0], pa[1][1], pa[1][2], pa[1][3], b2, b3);
            }
        }
    }

    // Epilogue: normalize, tf32-round (feeds O-projection), write [B,S,D]
#pragma unroll
    for (int mt = 0; mt < 2; mt++) {
        float i1 = 1.0f / ls[mt][0], i2 = 1.0f / ls[mt][1];
        const int row1 = q0 + mrow + mt * 16 + r;
#pragma unroll
        for (int nt = 0; nt < 8; nt++) {
            int col = h * HS + nt * 8 + 2 * q;
            *(float2*)&O[(b * SEQ + row1) * DIM + col] =
                make_float2(tf32rn(oacc[mt][nt][0] * i1), tf32rn(oacc[mt][nt][1] * i1));
            *(float2*)&O[(b * SEQ + row1 + 8) * DIM + col] =
                make_float2(tf32rn(oacc[mt][nt][2] * i2), tf32rn(oacc[mt][nt][3] * i2));
        }
    }
}

// ---------------------------------------------------------------------------
extern "C" void kernel_launch(void* const* d_in, const int* in_sizes, int n_in,
                              void* d_out, int out_size)
{
    const float* x  = (const float*)d_in[0];
    const float* Wq = (const float*)d_in[1];
    const float* bq = (const float*)d_in[2];
    const float* Wk = (const float*)d_in[3];
    const float* bk = (const float*)d_in[4];
    const float* Wv = (const float*)d_in[5];
    const float* bv = (const float*)d_in[6];
    const float* Wo = (const float*)d_in[7];
    const float* bo = (const float*)d_in[8];
    float* out = (float*)d_out;

    float *Qp, *Kp, *Vp, *Ap, *Xp, *WTp;
    cudaGetSymbolAddress((void**)&Qp,  g_Q);
    cudaGetSymbolAddress((void**)&Kp,  g_K);
    cudaGetSymbolAddress((void**)&Vp,  g_V);
    cudaGetSymbolAddress((void**)&Ap,  g_A);
    cudaGetSymbolAddress((void**)&Xp,  g_X);
    cudaGetSymbolAddress((void**)&WTp, g_WT);

    const int GEMM_SMEM  = 4 * GTILEB;            // 73,728
    const int FLASH_SMEM = (4*64*68 + 128*68)*4;  // 104,448
    cudaFuncSetAttribute(gemm_tc,    cudaFuncAttributeMaxDynamicSharedMemorySize, GEMM_SMEM);
    cudaFuncSetAttribute(flash_attn, cudaFuncAttributeMaxDynamicSharedMemorySize, FLASH_SMEM);

    round_x_k<<<(MTOT * DIM / 4 + 255) / 256, 256>>>(x, Xp, MTOT * DIM);
    transpose_w<<<dim3(DIM / 32, DIM / 32, 4), dim3(32, 8)>>>(Wq, Wk, Wv, Wo, WTp);

    // hs^-0.5 * log2(e) folded into Q (softmax runs in exp2 domain)
    const float qscale = 0.125f * 1.44269504088896340736f;

    // Fused Q/K/V projection: grid.x spans 3*768 cols
    dim3 gridQKV(3 * DIM / 128, MTOT / 128);   // (18, 64)
    gemm_tc<<<gridQKV, 256, GEMM_SMEM>>>(Xp, WTp, bq, bk, bv, Qp, Kp, Vp, 1, qscale);

    dim3 gridF(SEQ / 128, HEADS, BATCH);       // (16, 12, 4)
    flash_attn<<<gridF, 128, FLASH_SMEM>>>(Qp, Kp, Vp, Ap);

    dim3 gridO(DIM / 128, MTOT / 128);         // (6, 64)
    gemm_tc<<<gridO, 256, GEMM_SMEM>>>(Ap, WTp + 3 * DIM * DIM, bo, bo, bo,
                                       out, out, out, 0, 1.0f);
}

// round 7
// speedup vs baseline: 7.6820x; 1.6843x over previous
#include <cuda_runtime.h>
#include <cuda_fp16.h>
#include <cstdint>
#include <math.h>

#define BATCH 4
#define SEQ   2048
#define DIM   768
#define HEADS 12
#define HS    64
#define MTOT  (BATCH*SEQ)
#define GK    DIM

// Scratch (allocation-free: __device__ globals), all fp16
static __device__ __half g_Qh[BATCH*HEADS*SEQ*HS];
static __device__ __half g_Kh[BATCH*HEADS*SEQ*HS];
static __device__ __half g_Vh[BATCH*HEADS*SEQ*HS];   // [B,H,hs,S] (transposed)
static __device__ __half g_Ah[MTOT*DIM];             // attention output, fp16
static __device__ __half g_Xh[MTOT*DIM];             // fp16 x
static __device__ __half g_WTh[4*DIM*DIM];           // fp16 W^T (N x K row-major)

// ---------------------------------------------------------------------------
// Helpers
// ---------------------------------------------------------------------------
__device__ __forceinline__ uint32_t s2u(const void* p) {
    uint32_t a;
    asm("{ .reg .u64 t; cvta.to.shared.u64 t, %1; cvt.u32.u64 %0, t; }"
        : "=r"(a) : "l"(p));
    return a;
}
__device__ __forceinline__ float ex2f(float x) {
    float y;
    asm("ex2.approx.ftz.f32 %0, %1;" : "=f"(y) : "f"(x));
    return y;
}
__device__ __forceinline__ void cp16(uint32_t dst, const void* src) {
    asm volatile("cp.async.cg.shared.global [%0], [%1], 16;"
                 :: "r"(dst), "l"(src) : "memory");
}
#define CP_COMMIT asm volatile("cp.async.commit_group;" ::: "memory")
#define CP_WAIT0  asm volatile("cp.async.wait_group 0;" ::: "memory")

__device__ __forceinline__ void ldsm4(uint32_t& r0, uint32_t& r1, uint32_t& r2,
                                      uint32_t& r3, uint32_t a) {
    asm volatile("ldmatrix.sync.aligned.m8n8.x4.shared.b16 {%0,%1,%2,%3}, [%4];"
        : "=r"(r0), "=r"(r1), "=r"(r2), "=r"(r3) : "r"(a));
}

// D += A * B  (m16n8k16 f16, f32 accumulate)
__device__ __forceinline__ void mma_f16(float* d, uint32_t a0, uint32_t a1,
                                        uint32_t a2, uint32_t a3,
                                        uint32_t b0, uint32_t b1) {
    asm volatile(
        "mma.sync.aligned.m16n8k16.row.col.f32.f16.f16.f32 "
        "{%0,%1,%2,%3}, {%4,%5,%6,%7}, {%8,%9}, {%0,%1,%2,%3};"
        : "+f"(d[0]), "+f"(d[1]), "+f"(d[2]), "+f"(d[3])
        : "r"(a0), "r"(a1), "r"(a2), "r"(a3), "r"(b0), "r"(b1));
}

// ---------------------------------------------------------------------------
// Prep kernels: x -> fp16; W -> fp16 transposed (N x K)
// ---------------------------------------------------------------------------
__global__ void conv_x_h(const float* __restrict__ x, __half* __restrict__ y, int n) {
    int i = (blockIdx.x * blockDim.x + threadIdx.x) * 4;
    if (i < n) {
        float4 v = *(const float4*)&x[i];
        *(__half2*)&y[i]     = __floats2half2_rn(v.x, v.y);
        *(__half2*)&y[i + 2] = __floats2half2_rn(v.z, v.w);
    }
}

__global__ void transpose_w_h(const float* __restrict__ W0, const float* __restrict__ W1,
                              const float* __restrict__ W2, const float* __restrict__ W3,
                              __half* __restrict__ WT) {
    __shared__ float t[32][33];
    const float* W = (blockIdx.z == 0) ? W0 : (blockIdx.z == 1) ? W1
                   : (blockIdx.z == 2) ? W2 : W3;
    __half* O = WT + blockIdx.z * DIM * DIM;
    int k0 = blockIdx.y * 32, n0 = blockIdx.x * 32;
    for (int r = threadIdx.y; r < 32; r += 8)
        t[r][threadIdx.x] = W[(k0 + r) * DIM + n0 + threadIdx.x];
    __syncthreads();
    for (int r = threadIdx.y; r < 32; r += 8)
        O[(n0 + r) * DIM + k0 + threadIdx.x] = __float2half_rn(t[threadIdx.x][r]);
}

// ---------------------------------------------------------------------------
// fp16 warp-MMA GEMM (f32 accum): C = (A[M,K] @ Bt[N,K]^T + bias) * scale
//  fused=1: grid.x=18, which=bx/6: Q,K headed half [B,H,S,hs]; V half [B,H,hs,S]
//  fused=0: grid.x=6, plain f32 C0 = A @ Bt^T + bias0
// CTA 128x128, BK=32 (2 k16-steps), 8 warps (4m x 2n), warp 32x64.
// smem rows padded to 40 halves (80B): ldsm phases conflict-free.
// ---------------------------------------------------------------------------
#define HSTB   80           // smem row stride bytes (40 halves)
#define HTILEB (128*HSTB)   // 10240

__global__ __launch_bounds__(256, 2)
void gemm_h(const __half* __restrict__ A, const __half* __restrict__ Bt,
            const float* __restrict__ bias0, const float* __restrict__ bias1,
            const float* __restrict__ bias2,
            void* __restrict__ C0v, __half* __restrict__ C1, __half* __restrict__ C2,
            int fused, float qscale)
{
    extern __shared__ __half smh[];
    const int tid = threadIdx.x;
    const int wid = tid >> 5, lane = tid & 31;
    const int wm = wid & 3, wn = wid >> 2;
    const int r = lane >> 2, q = lane & 3;
    const int m0 = blockIdx.y * 128;
    const uint32_t sbase = s2u(smh);

    const int lrA = (lane & 7) + ((lane >> 3) & 1) * 8;
    const int loA = ((lane >> 4) & 1) * 16;
    const int lrB = (lane & 7) + ((lane >> 4) & 1) * 8;
    const int loB = ((lane >> 3) & 1) * 16;
    uint32_t offA[2], offB[4];
#pragma unroll
    for (int mt = 0; mt < 2; mt++)
        offA[mt] = (uint32_t)((wm * 32 + mt * 16 + lrA) * HSTB + loA);
#pragma unroll
    for (int p = 0; p < 4; p++)
        offB[p] = (uint32_t)((wn * 64 + p * 16 + lrB) * HSTB + loB);

    float acc[2][8][4];
#pragma unroll
    for (int mt = 0; mt < 2; mt++)
#pragma unroll
        for (int nt = 0; nt < 8; nt++)
#pragma unroll
            for (int j = 0; j < 4; j++) acc[mt][nt][j] = 0.f;

    const int btrow0 = blockIdx.x * 128;
    auto load_tiles = [&](int kc, int buf) {
        uint32_t ab = sbase + (uint32_t)buf * 2u * HTILEB;
        uint32_t bb = ab + HTILEB;
#pragma unroll
        for (int i = 0; i < 2; i++) {
            int e = tid + i * 256;              // 512 cp16 per tile
            int row = e >> 2, seg = e & 3;      // 4 x 16B = 32 halves/row
            cp16(ab + row * HSTB + seg * 16, A  + (m0 + row) * GK + kc + seg * 8);
            cp16(bb + row * HSTB + seg * 16, Bt + (btrow0 + row) * GK + kc + seg * 8);
        }
    };

    load_tiles(0, 0);
    CP_COMMIT;

    const int NIT = GK / 32;   // 24
    for (int it = 0; it < NIT; it++) {
        CP_WAIT0;
        __syncthreads();
        if (it + 1 < NIT) { load_tiles((it + 1) * 32, (it + 1) & 1); CP_COMMIT; }

        const uint32_t baseA = sbase + (uint32_t)(it & 1) * 2u * HTILEB;
        const uint32_t baseB = baseA + HTILEB;
#pragma unroll
        for (int ks = 0; ks < 2; ks++) {        // 2 x k16
            uint32_t a[2][4];
            ldsm4(a[0][0], a[0][1], a[0][2], a[0][3], baseA + offA[0] + ks * 32);
            ldsm4(a[1][0], a[1][1], a[1][2], a[1][3], baseA + offA[1] + ks * 32);
#pragma unroll
            for (int p = 0; p < 4; p++) {
                uint32_t b0, b1, b2, b3;
                ldsm4(b0, b1, b2, b3, baseB + offB[p] + ks * 32);
                mma_f16(acc[0][2*p    ], a[0][0], a[0][1], a[0][2], a[0][3], b0, b1);
                mma_f16(acc[1][2*p    ], a[1][0], a[1][1], a[1][2], a[1][3], b0, b1);
                mma_f16(acc[0][2*p + 1], a[0][0], a[0][1], a[0][2], a[0][3], b2, b3);
                mma_f16(acc[1][2*p + 1], a[1][0], a[1][1], a[1][2], a[1][3], b2, b3);
            }
        }
    }

    int which = 0, nloc0 = blockIdx.x * 128;
    const float* bias = bias0;
    float scale = 1.f;
    if (fused) {
        which = blockIdx.x / 6;
        nloc0 = (blockIdx.x % 6) * 128;
        bias  = (which == 0) ? bias0 : (which == 1) ? bias1 : bias2;
        scale = (which == 0) ? qscale : 1.f;
    }

#pragma unroll
    for (int mt = 0; mt < 2; mt++) {
        int row = m0 + wm * 32 + mt * 16 + r;
#pragma unroll
        for (int nt = 0; nt < 8; nt++) {
            int col = nloc0 + wn * 64 + nt * 8 + 2 * q;
            float b0v = bias[col], b1v = bias[col + 1];
            float v0 = (acc[mt][nt][0] + b0v) * scale;
            float v1 = (acc[mt][nt][1] + b1v) * scale;
            float v2 = (acc[mt][nt][2] + b0v) * scale;
            float v3 = (acc[mt][nt][3] + b1v) * scale;
            if (!fused) {
                float* C0 = (float*)C0v;
                *(float2*)&C0[row * DIM + col]       = make_float2(v0, v1);
                *(float2*)&C0[(row + 8) * DIM + col] = make_float2(v2, v3);
            } else {
                int b = row >> 11;
                int h = col >> 6, d = col & 63;
                int s1 = row & 2047, s2 = s1 + 8;
                if (which < 2) {
                    __half* Cc = which ? C1 : (__half*)C0v;
                    __half* base = Cc + ((size_t)(b * HEADS + h) * SEQ) * HS + d;
                    *(__half2*)&base[s1 * HS] = __floats2half2_rn(v0, v1);
                    *(__half2*)&base[s2 * HS] = __floats2half2_rn(v2, v3);
                } else {
                    __half* base = C2 + ((size_t)(b * HEADS + h) * HS + d) * SEQ;
                    base[s1]       = __float2half_rn(v0);
                    base[SEQ + s1] = __float2half_rn(v1);
                    base[s2]       = __float2half_rn(v2);
                    base[SEQ + s2] = __float2half_rn(v3);
                }
            }
        }
    }
}

// ---------------------------------------------------------------------------
// Flash attention fp16 (f32 accum): 8 warps x 16 q-rows, 256 threads,
// 64-key tiles, cp.async double buffer, warp-private P rows.
// smem (halves, rows padded to 72 = 144B): Ks[2][64*72] Vs[2][64*72] Ps[128*72]
// total 55,296 B -> 2 CTAs/SM with <=128 regs.
// ---------------------------------------------------------------------------
#define FH   144            // bytes per row (72 halves)
#define FKV  (64*FH)        // 9216

__global__ __launch_bounds__(256, 2)
void flash_h(const __half* __restrict__ Q, const __half* __restrict__ K,
             const __half* __restrict__ V, __half* __restrict__ O)
{
    extern __shared__ __half fs[];
    __half* Ps = fs + (4 * FKV) / 2;

    const int tid = threadIdx.x;
    const int wid = tid >> 5, lane = tid & 31;
    const int r = lane >> 2, q = lane & 3;
    const int mrow = wid * 16;
    const int q0 = blockIdx.x * 128, h = blockIdx.y, b = blockIdx.z;

    const __half* Qg = Q + ((size_t)(b * HEADS + h) * SEQ + q0) * HS;
    const __half* Kg = K + ((size_t)(b * HEADS + h) * SEQ) * HS;
    const __half* Vg = V + ((size_t)(b * HEADS + h) * HS) * SEQ;

    const uint32_t kbase = s2u(fs);
    const uint32_t vbase = kbase + 2 * FKV;
    const uint32_t pbase = kbase + 4 * FKV;

    const int lrA = (lane & 7) + ((lane >> 3) & 1) * 8;
    const int loA = ((lane >> 4) & 1) * 16;
    const int lrB = (lane & 7) + ((lane >> 4) & 1) * 8;
    const int loB = ((lane >> 3) & 1) * 16;
    const uint32_t offA = (uint32_t)((mrow + lrA) * FH + loA);
    uint32_t offB[4];
#pragma unroll
    for (int p = 0; p < 4; p++)
        offB[p] = (uint32_t)((p * 16 + lrB) * FH + loB);

    auto load_kv = [&](int t, int buf) {
        uint32_t kb = kbase + (uint32_t)buf * FKV;
        uint32_t vb = vbase + (uint32_t)buf * FKV;
#pragma unroll
        for (int i = 0; i < 2; i++) {
            int e = tid + i * 256;          // 512 cp16 per tile
            int row = e >> 3, seg = e & 7;  // 8 x 16B = 64 halves/row
            cp16(kb + row * FH + seg * 16, Kg + (t * 64 + row) * HS + seg * 8);
            cp16(vb + row * FH + seg * 16, Vg + row * SEQ + t * 64 + seg * 8);
        }
    };

    load_kv(0, 0);
    CP_COMMIT;

    // Stage Q -> Ps (16B vector copies), then persistent A-fragments
#pragma unroll
    for (int i = 0; i < 4; i++) {
        int e = tid + i * 256;              // 1024 x 8 halves
        int row = e >> 3, seg = e & 7;
        *(uint4*)(Ps + row * 72 + seg * 8) = *(const uint4*)(Qg + row * HS + seg * 8);
    }
    __syncthreads();
    uint32_t qf[4][4];
#pragma unroll
    for (int ks = 0; ks < 4; ks++)
        ldsm4(qf[ks][0], qf[ks][1], qf[ks][2], qf[ks][3], pbase + offA + ks * 32);

    float m1 = -1e30f, m2 = -1e30f, l1 = 0.f, l2 = 0.f;
    float oacc[8][4];
#pragma unroll
    for (int nt = 0; nt < 8; nt++)
#pragma unroll
        for (int j = 0; j < 4; j++) oacc[nt][j] = 0.f;

    const int NT = SEQ / 64;  // 32
    for (int t = 0; t < NT; t++) {
        CP_WAIT0;
        __syncthreads();
        if (t + 1 < NT) { load_kv(t + 1, (t + 1) & 1); CP_COMMIT; }

        const uint32_t kb = kbase + (uint32_t)(t & 1) * FKV;
        const uint32_t vb = vbase + (uint32_t)(t & 1) * FKV;

        // S = Q @ K^T  (4 k16-steps)
        float sacc[8][4];
#pragma unroll
        for (int nt = 0; nt < 8; nt++)
#pragma unroll
            for (int j = 0; j < 4; j++) sacc[nt][j] = 0.f;
#pragma unroll
        for (int ks = 0; ks < 4; ks++) {
#pragma unroll
            for (int p = 0; p < 4; p++) {
                uint32_t b0, b1, b2, b3;
                ldsm4(b0, b1, b2, b3, kb + offB[p] + ks * 32);
                mma_f16(sacc[2*p    ], qf[ks][0], qf[ks][1], qf[ks][2], qf[ks][3], b0, b1);
                mma_f16(sacc[2*p + 1], qf[ks][0], qf[ks][1], qf[ks][2], qf[ks][3], b2, b3);
            }
        }

        // Online softmax (exp2 domain; rows mrow+r, mrow+r+8)
        float mt1 = -1e30f, mt2 = -1e30f;
#pragma unroll
        for (int nt = 0; nt < 8; nt++) {
            mt1 = fmaxf(mt1, fmaxf(sacc[nt][0], sacc[nt][1]));
            mt2 = fmaxf(mt2, fmaxf(sacc[nt][2], sacc[nt][3]));
        }
        mt1 = fmaxf(mt1, __shfl_xor_sync(0xffffffffu, mt1, 1));
        mt1 = fmaxf(mt1, __shfl_xor_sync(0xffffffffu, mt1, 2));
        mt2 = fmaxf(mt2, __shfl_xor_sync(0xffffffffu, mt2, 1));
        mt2 = fmaxf(mt2, __shfl_xor_sync(0xffffffffu, mt2, 2));
        float mn1 = fmaxf(m1, mt1), mn2 = fmaxf(m2, mt2);
        float c1 = ex2f(m1 - mn1), c2 = ex2f(m2 - mn2);
        m1 = mn1; m2 = mn2;
        float rs1 = 0.f, rs2 = 0.f;
#pragma unroll
        for (int nt = 0; nt < 8; nt++) {
            sacc[nt][0] = ex2f(sacc[nt][0] - mn1); rs1 += sacc[nt][0];
            sacc[nt][1] = ex2f(sacc[nt][1] - mn1); rs1 += sacc[nt][1];
            sacc[nt][2] = ex2f(sacc[nt][2] - mn2); rs2 += sacc[nt][2];
            sacc[nt][3] = ex2f(sacc[nt][3] - mn2); rs2 += sacc[nt][3];
        }
        rs1 += __shfl_xor_sync(0xffffffffu, rs1, 1);
        rs1 += __shfl_xor_sync(0xffffffffu, rs1, 2);
        rs2 += __shfl_xor_sync(0xffffffffu, rs2, 1);
        rs2 += __shfl_xor_sync(0xffffffffu, rs2, 2);
        l1 = l1 * c1 + rs1;
        l2 = l2 * c2 + rs2;
#pragma unroll
        for (int nt = 0; nt < 8; nt++) {
            oacc[nt][0] *= c1; oacc[nt][1] *= c1;
            oacc[nt][2] *= c2; oacc[nt][3] *= c2;
        }

        // P -> warp-private smem rows (fp16)
        const int pr1 = (mrow + r) * 72, pr2 = pr1 + 8 * 72;
#pragma unroll
        for (int nt = 0; nt < 8; nt++) {
            *(__half2*)&Ps[pr1 + nt * 8 + 2 * q] = __floats2half2_rn(sacc[nt][0], sacc[nt][1]);
            *(__half2*)&Ps[pr2 + nt * 8 + 2 * q] = __floats2half2_rn(sacc[nt][2], sacc[nt][3]);
        }
        __syncwarp();

        // O += P @ V   (V smem rows = d, cols = key)
#pragma unroll
        for (int ks = 0; ks < 4; ks++) {
            uint32_t pa0, pa1, pa2, pa3;
            ldsm4(pa0, pa1, pa2, pa3, pbase + offA + ks * 32);
#pragma unroll
            for (int p = 0; p < 4; p++) {
                uint32_t b0, b1, b2, b3;
                ldsm4(b0, b1, b2, b3, vb + offB[p] + ks * 32);
                mma_f16(oacc[2*p    ], pa0, pa1, pa2, pa3, b0, b1);
                mma_f16(oacc[2*p + 1], pa0, pa1, pa2, pa3, b2, b3);
            }
        }
    }

    // Epilogue: normalize, write fp16 [B,S,D] (feeds O-projection)
    float i1 = 1.0f / l1, i2 = 1.0f / l2;
    const int row1 = q0 + mrow + r;
#pragma unroll
    for (int nt = 0; nt < 8; nt++) {
        int col = h * HS + nt * 8 + 2 * q;
        *(__half2*)&O[(size_t)(b * SEQ + row1) * DIM + col] =
            __floats2half2_rn(oacc[nt][0] * i1, oacc[nt][1] * i1);
        *(__half2*)&O[(size_t)(b * SEQ + row1 + 8) * DIM + col] =
            __floats2half2_rn(oacc[nt][2] * i2, oacc[nt][3] * i2);
    }
}

// ---------------------------------------------------------------------------
extern "C" void kernel_launch(void* const* d_in, const int* in_sizes, int n_in,
                              void* d_out, int out_size)
{
    const float* x  = (const float*)d_in[0];
    const float* Wq = (const float*)d_in[1];
    const float* bq = (const float*)d_in[2];
    const float* Wk = (const float*)d_in[3];
    const float* bk = (const float*)d_in[4];
    const float* Wv = (const float*)d_in[5];
    const float* bv = (const float*)d_in[6];
    const float* Wo = (const float*)d_in[7];
    const float* bo = (const float*)d_in[8];
    float* out = (float*)d_out;

    __half *Qp, *Kp, *Vp, *Ap, *Xp, *WTp;
    cudaGetSymbolAddress((void**)&Qp,  g_Qh);
    cudaGetSymbolAddress((void**)&Kp,  g_Kh);
    cudaGetSymbolAddress((void**)&Vp,  g_Vh);
    cudaGetSymbolAddress((void**)&Ap,  g_Ah);
    cudaGetSymbolAddress((void**)&Xp,  g_Xh);
    cudaGetSymbolAddress((void**)&WTp, g_WTh);

    const int GEMM_SMEM  = 4 * HTILEB;               // 40,960
    const int FLASH_SMEM = 4 * FKV + 128 * FH;       // 55,296
    cudaFuncSetAttribute(gemm_h,  cudaFuncAttributeMaxDynamicSharedMemorySize, GEMM_SMEM);
    cudaFuncSetAttribute(flash_h, cudaFuncAttributeMaxDynamicSharedMemorySize, FLASH_SMEM);

    conv_x_h<<<(MTOT * DIM / 4 + 255) / 256, 256>>>(x, Xp, MTOT * DIM);
    transpose_w_h<<<dim3(DIM / 32, DIM / 32, 4), dim3(32, 8)>>>(Wq, Wk, Wv, Wo, WTp);

    // hs^-0.5 * log2(e) folded into Q (softmax runs in exp2 domain)
    const float qscale = 0.125f * 1.44269504088896340736f;

    dim3 gridQKV(3 * DIM / 128, MTOT / 128);   // (18, 64)
    gemm_h<<<gridQKV, 256, GEMM_SMEM>>>(Xp, WTp, bq, bk, bv, Qp, Kp, Vp, 1, qscale);

    dim3 gridF(SEQ / 128, HEADS, BATCH);       // (16, 12, 4)
    flash_h<<<gridF, 256, FLASH_SMEM>>>(Qp, Kp, Vp, Ap);

    dim3 gridO(DIM / 128, MTOT / 128);         // (6, 64)
    gemm_h<<<gridO, 256, GEMM_SMEM>>>(Ap, WTp + 3 * DIM * DIM, bo, bo, bo,
                                      out, Kp, Vp, 0, 1.0f);
}

// round 8
// speedup vs baseline: 8.0651x; 1.0499x over previous
#include <cuda_runtime.h>
#include <cuda_fp16.h>
#include <cstdint>
#include <math.h>

#define BATCH 4
#define SEQ   2048
#define DIM   768
#define HEADS 12
#define HS    64
#define MTOT  (BATCH*SEQ)
#define GK    DIM

// Scratch (allocation-free: __device__ globals), all fp16
static __device__ __half g_Qh[BATCH*HEADS*SEQ*HS];
static __device__ __half g_Kh[BATCH*HEADS*SEQ*HS];
static __device__ __half g_Vh[BATCH*HEADS*SEQ*HS];   // [B,H,hs,S] (transposed)
static __device__ __half g_Ah[MTOT*DIM];             // attention output, fp16
static __device__ __half g_Xh[MTOT*DIM];             // fp16 x
static __device__ __half g_WTh[4*DIM*DIM];           // fp16 W^T (N x K row-major)

// ---------------------------------------------------------------------------
// Helpers
// ---------------------------------------------------------------------------
__device__ __forceinline__ uint32_t s2u(const void* p) {
    uint32_t a;
    asm("{ .reg .u64 t; cvta.to.shared.u64 t, %1; cvt.u32.u64 %0, t; }"
        : "=r"(a) : "l"(p));
    return a;
}
__device__ __forceinline__ float ex2f(float x) {
    float y;
    asm("ex2.approx.ftz.f32 %0, %1;" : "=f"(y) : "f"(x));
    return y;
}
__device__ __forceinline__ uint32_t packh2(float lo, float hi) {
    __half2 h = __floats2half2_rn(lo, hi);
    return *(uint32_t*)&h;
}
__device__ __forceinline__ void cp16(uint32_t dst, const void* src) {
    asm volatile("cp.async.cg.shared.global [%0], [%1], 16;"
                 :: "r"(dst), "l"(src) : "memory");
}
#define CP_COMMIT asm volatile("cp.async.commit_group;" ::: "memory")
#define CP_WAIT0  asm volatile("cp.async.wait_group 0;" ::: "memory")

__device__ __forceinline__ void ldsm4(uint32_t& r0, uint32_t& r1, uint32_t& r2,
                                      uint32_t& r3, uint32_t a) {
    asm volatile("ldmatrix.sync.aligned.m8n8.x4.shared.b16 {%0,%1,%2,%3}, [%4];"
        : "=r"(r0), "=r"(r1), "=r"(r2), "=r"(r3) : "r"(a));
}

// D += A * B  (m16n8k16 f16, f32 accumulate)
__device__ __forceinline__ void mma_f16(float* d, uint32_t a0, uint32_t a1,
                                        uint32_t a2, uint32_t a3,
                                        uint32_t b0, uint32_t b1) {
    asm volatile(
        "mma.sync.aligned.m16n8k16.row.col.f32.f16.f16.f32 "
        "{%0,%1,%2,%3}, {%4,%5,%6,%7}, {%8,%9}, {%0,%1,%2,%3};"
        : "+f"(d[0]), "+f"(d[1]), "+f"(d[2]), "+f"(d[3])
        : "r"(a0), "r"(a1), "r"(a2), "r"(a3), "r"(b0), "r"(b1));
}

// ---------------------------------------------------------------------------
// Prep kernels: x -> fp16; W -> fp16 transposed (N x K)
// ---------------------------------------------------------------------------
__global__ void conv_x_h(const float* __restrict__ x, __half* __restrict__ y, int n) {
    int i = (blockIdx.x * blockDim.x + threadIdx.x) * 4;
    if (i < n) {
        float4 v = *(const float4*)&x[i];
        *(__half2*)&y[i]     = __floats2half2_rn(v.x, v.y);
        *(__half2*)&y[i + 2] = __floats2half2_rn(v.z, v.w);
    }
}

__global__ void transpose_w_h(const float* __restrict__ W0, const float* __restrict__ W1,
                              const float* __restrict__ W2, const float* __restrict__ W3,
                              __half* __restrict__ WT) {
    __shared__ float t[32][33];
    const float* W = (blockIdx.z == 0) ? W0 : (blockIdx.z == 1) ? W1
                   : (blockIdx.z == 2) ? W2 : W3;
    __half* O = WT + blockIdx.z * DIM * DIM;
    int k0 = blockIdx.y * 32, n0 = blockIdx.x * 32;
    for (int r = threadIdx.y; r < 32; r += 8)
        t[r][threadIdx.x] = W[(k0 + r) * DIM + n0 + threadIdx.x];
    __syncthreads();
    for (int r = threadIdx.y; r < 32; r += 8)
        O[(n0 + r) * DIM + k0 + threadIdx.x] = __float2half_rn(t[threadIdx.x][r]);
}

// ---------------------------------------------------------------------------
// fp16 warp-MMA GEMM (unchanged from R7)
// ---------------------------------------------------------------------------
#define HSTB   80           // smem row stride bytes (40 halves)
#define HTILEB (128*HSTB)   // 10240

__global__ __launch_bounds__(256, 2)
void gemm_h(const __half* __restrict__ A, const __half* __restrict__ Bt,
            const float* __restrict__ bias0, const float* __restrict__ bias1,
            const float* __restrict__ bias2,
            void* __restrict__ C0v, __half* __restrict__ C1, __half* __restrict__ C2,
            int fused, float qscale)
{
    extern __shared__ __half smh[];
    const int tid = threadIdx.x;
    const int wid = tid >> 5, lane = tid & 31;
    const int wm = wid & 3, wn = wid >> 2;
    const int r = lane >> 2, q = lane & 3;
    const int m0 = blockIdx.y * 128;
    const uint32_t sbase = s2u(smh);

    const int lrA = (lane & 7) + ((lane >> 3) & 1) * 8;
    const int loA = ((lane >> 4) & 1) * 16;
    const int lrB = (lane & 7) + ((lane >> 4) & 1) * 8;
    const int loB = ((lane >> 3) & 1) * 16;
    uint32_t offA[2], offB[4];
#pragma unroll
    for (int mt = 0; mt < 2; mt++)
        offA[mt] = (uint32_t)((wm * 32 + mt * 16 + lrA) * HSTB + loA);
#pragma unroll
    for (int p = 0; p < 4; p++)
        offB[p] = (uint32_t)((wn * 64 + p * 16 + lrB) * HSTB + loB);

    float acc[2][8][4];
#pragma unroll
    for (int mt = 0; mt < 2; mt++)
#pragma unroll
        for (int nt = 0; nt < 8; nt++)
#pragma unroll
            for (int j = 0; j < 4; j++) acc[mt][nt][j] = 0.f;

    const int btrow0 = blockIdx.x * 128;
    auto load_tiles = [&](int kc, int buf) {
        uint32_t ab = sbase + (uint32_t)buf * 2u * HTILEB;
        uint32_t bb = ab + HTILEB;
#pragma unroll
        for (int i = 0; i < 2; i++) {
            int e = tid + i * 256;
            int row = e >> 2, seg = e & 3;
            cp16(ab + row * HSTB + seg * 16, A  + (m0 + row) * GK + kc + seg * 8);
            cp16(bb + row * HSTB + seg * 16, Bt + (btrow0 + row) * GK + kc + seg * 8);
        }
    };

    load_tiles(0, 0);
    CP_COMMIT;

    const int NIT = GK / 32;   // 24
    for (int it = 0; it < NIT; it++) {
        CP_WAIT0;
        __syncthreads();
        if (it + 1 < NIT) { load_tiles((it + 1) * 32, (it + 1) & 1); CP_COMMIT; }

        const uint32_t baseA = sbase + (uint32_t)(it & 1) * 2u * HTILEB;
        const uint32_t baseB = baseA + HTILEB;
#pragma unroll
        for (int ks = 0; ks < 2; ks++) {
            uint32_t a[2][4];
            ldsm4(a[0][0], a[0][1], a[0][2], a[0][3], baseA + offA[0] + ks * 32);
            ldsm4(a[1][0], a[1][1], a[1][2], a[1][3], baseA + offA[1] + ks * 32);
#pragma unroll
            for (int p = 0; p < 4; p++) {
                uint32_t b0, b1, b2, b3;
                ldsm4(b0, b1, b2, b3, baseB + offB[p] + ks * 32);
                mma_f16(acc[0][2*p    ], a[0][0], a[0][1], a[0][2], a[0][3], b0, b1);
                mma_f16(acc[1][2*p    ], a[1][0], a[1][1], a[1][2], a[1][3], b0, b1);
                mma_f16(acc[0][2*p + 1], a[0][0], a[0][1], a[0][2], a[0][3], b2, b3);
                mma_f16(acc[1][2*p + 1], a[1][0], a[1][1], a[1][2], a[1][3], b2, b3);
            }
        }
    }

    int which = 0, nloc0 = blockIdx.x * 128;
    const float* bias = bias0;
    float scale = 1.f;
    if (fused) {
        which = blockIdx.x / 6;
        nloc0 = (blockIdx.x % 6) * 128;
        bias  = (which == 0) ? bias0 : (which == 1) ? bias1 : bias2;
        scale = (which == 0) ? qscale : 1.f;
    }

#pragma unroll
    for (int mt = 0; mt < 2; mt++) {
        int row = m0 + wm * 32 + mt * 16 + r;
#pragma unroll
        for (int nt = 0; nt < 8; nt++) {
            int col = nloc0 + wn * 64 + nt * 8 + 2 * q;
            float b0v = bias[col], b1v = bias[col + 1];
            float v0 = (acc[mt][nt][0] + b0v) * scale;
            float v1 = (acc[mt][nt][1] + b1v) * scale;
            float v2 = (acc[mt][nt][2] + b0v) * scale;
            float v3 = (acc[mt][nt][3] + b1v) * scale;
            if (!fused) {
                float* C0 = (float*)C0v;
                *(float2*)&C0[row * DIM + col]       = make_float2(v0, v1);
                *(float2*)&C0[(row + 8) * DIM + col] = make_float2(v2, v3);
            } else {
                int b = row >> 11;
                int h = col >> 6, d = col & 63;
                int s1 = row & 2047, s2 = s1 + 8;
                if (which < 2) {
                    __half* Cc = which ? C1 : (__half*)C0v;
                    __half* base = Cc + ((size_t)(b * HEADS + h) * SEQ) * HS + d;
                    *(__half2*)&base[s1 * HS] = __floats2half2_rn(v0, v1);
                    *(__half2*)&base[s2 * HS] = __floats2half2_rn(v2, v3);
                } else {
                    __half* base = C2 + ((size_t)(b * HEADS + h) * HS + d) * SEQ;
                    base[s1]       = __float2half_rn(v0);
                    base[SEQ + s1] = __float2half_rn(v1);
                    base[s2]       = __float2half_rn(v2);
                    base[SEQ + s2] = __float2half_rn(v3);
                }
            }
        }
    }
}

// ---------------------------------------------------------------------------
// Flash attention fp16, FA2-style register-local P fragments (no smem
// round-trip: m16n8k16 C-layout == next A-layout). 8 warps x 16 q-rows,
// 256 threads, 64-key tiles, cp.async double buffer.
// smem: Ks[2][64*72h] + Vs[2][64*72h] = 36,864 B (Q staged via K region once).
// ---------------------------------------------------------------------------
#define FH   144            // bytes per row (72 halves)
#define FKV  (64*FH)        // 9216

__global__ __launch_bounds__(256, 2)
void flash_h(const __half* __restrict__ Q, const __half* __restrict__ K,
             const __half* __restrict__ V, __half* __restrict__ O)
{
    extern __shared__ __half fs[];

    const int tid = threadIdx.x;
    const int wid = tid >> 5, lane = tid & 31;
    const int r = lane >> 2, q = lane & 3;
    const int mrow = wid * 16;
    const int q0 = blockIdx.x * 128, h = blockIdx.y, b = blockIdx.z;

    const __half* Qg = Q + ((size_t)(b * HEADS + h) * SEQ + q0) * HS;
    const __half* Kg = K + ((size_t)(b * HEADS + h) * SEQ) * HS;
    const __half* Vg = V + ((size_t)(b * HEADS + h) * HS) * SEQ;

    const uint32_t kbase = s2u(fs);
    const uint32_t vbase = kbase + 2 * FKV;

    const int lrA = (lane & 7) + ((lane >> 3) & 1) * 8;
    const int loA = ((lane >> 4) & 1) * 16;
    const int lrB = (lane & 7) + ((lane >> 4) & 1) * 8;
    const int loB = ((lane >> 3) & 1) * 16;
    uint32_t offB[4];
#pragma unroll
    for (int p = 0; p < 4; p++)
        offB[p] = (uint32_t)((p * 16 + lrB) * FH + loB);

    // ---- Stage Q through the K-buffer region (fits exactly: 128*144B) ----
#pragma unroll
    for (int i = 0; i < 4; i++) {
        int e = tid + i * 256;
        int row = e >> 3, seg = e & 7;
        *(uint4*)((char*)fs + row * FH + seg * 16) =
            *(const uint4*)(Qg + row * HS + seg * 8);
    }
    __syncthreads();
    uint32_t qf[4][4];
    {
        const uint32_t offQ = (uint32_t)((mrow + lrA) * FH + loA);
#pragma unroll
        for (int ks = 0; ks < 4; ks++)
            ldsm4(qf[ks][0], qf[ks][1], qf[ks][2], qf[ks][3], kbase + offQ + ks * 32);
    }
    __syncthreads();   // all qf reads done before cp.async overwrites region

    auto load_kv = [&](int t, int buf) {
        uint32_t kb = kbase + (uint32_t)buf * FKV;
        uint32_t vb = vbase + (uint32_t)buf * FKV;
#pragma unroll
        for (int i = 0; i < 2; i++) {
            int e = tid + i * 256;
            int row = e >> 3, seg = e & 7;
            cp16(kb + row * FH + seg * 16, Kg + (t * 64 + row) * HS + seg * 8);
            cp16(vb + row * FH + seg * 16, Vg + row * SEQ + t * 64 + seg * 8);
        }
    };

    load_kv(0, 0);
    CP_COMMIT;

    float m1 = -1e30f, m2 = -1e30f, l1 = 0.f, l2 = 0.f;
    float oacc[8][4];
#pragma unroll
    for (int nt = 0; nt < 8; nt++)
#pragma unroll
        for (int j = 0; j < 4; j++) oacc[nt][j] = 0.f;

    const int NT = SEQ / 64;  // 32
    for (int t = 0; t < NT; t++) {
        CP_WAIT0;
        __syncthreads();
        if (t + 1 < NT) { load_kv(t + 1, (t + 1) & 1); CP_COMMIT; }

        const uint32_t kb = kbase + (uint32_t)(t & 1) * FKV;
        const uint32_t vb = vbase + (uint32_t)(t & 1) * FKV;

        // S = Q @ K^T  (4 k16-steps)
        float sacc[8][4];
#pragma unroll
        for (int nt = 0; nt < 8; nt++)
#pragma unroll
            for (int j = 0; j < 4; j++) sacc[nt][j] = 0.f;
#pragma unroll
        for (int ks = 0; ks < 4; ks++) {
#pragma unroll
            for (int p = 0; p < 4; p++) {
                uint32_t b0, b1, b2, b3;
                ldsm4(b0, b1, b2, b3, kb + offB[p] + ks * 32);
                mma_f16(sacc[2*p    ], qf[ks][0], qf[ks][1], qf[ks][2], qf[ks][3], b0, b1);
                mma_f16(sacc[2*p + 1], qf[ks][0], qf[ks][1], qf[ks][2], qf[ks][3], b2, b3);
            }
        }

        // Online softmax (exp2 domain; rows mrow+r, mrow+r+8)
        float mt1 = -1e30f, mt2 = -1e30f;
#pragma unroll
        for (int nt = 0; nt < 8; nt++) {
            mt1 = fmaxf(mt1, fmaxf(sacc[nt][0], sacc[nt][1]));
            mt2 = fmaxf(mt2, fmaxf(sacc[nt][2], sacc[nt][3]));
        }
        mt1 = fmaxf(mt1, __shfl_xor_sync(0xffffffffu, mt1, 1));
        mt1 = fmaxf(mt1, __shfl_xor_sync(0xffffffffu, mt1, 2));
        mt2 = fmaxf(mt2, __shfl_xor_sync(0xffffffffu, mt2, 1));
        mt2 = fmaxf(mt2, __shfl_xor_sync(0xffffffffu, mt2, 2));
        float mn1 = fmaxf(m1, mt1), mn2 = fmaxf(m2, mt2);
        float c1 = ex2f(m1 - mn1), c2 = ex2f(m2 - mn2);
        m1 = mn1; m2 = mn2;
        float rs1 = 0.f, rs2 = 0.f;
#pragma unroll
        for (int nt = 0; nt < 8; nt++) {
            sacc[nt][0] = ex2f(sacc[nt][0] - mn1); rs1 += sacc[nt][0];
            sacc[nt][1] = ex2f(sacc[nt][1] - mn1); rs1 += sacc[nt][1];
            sacc[nt][2] = ex2f(sacc[nt][2] - mn2); rs2 += sacc[nt][2];
            sacc[nt][3] = ex2f(sacc[nt][3] - mn2); rs2 += sacc[nt][3];
        }
        rs1 += __shfl_xor_sync(0xffffffffu, rs1, 1);
        rs1 += __shfl_xor_sync(0xffffffffu, rs1, 2);
        rs2 += __shfl_xor_sync(0xffffffffu, rs2, 1);
        rs2 += __shfl_xor_sync(0xffffffffu, rs2, 2);
        l1 = l1 * c1 + rs1;
        l2 = l2 * c2 + rs2;
#pragma unroll
        for (int nt = 0; nt < 8; nt++) {
            oacc[nt][0] *= c1; oacc[nt][1] *= c1;
            oacc[nt][2] *= c2; oacc[nt][3] *= c2;
        }

        // O += P @ V : P A-fragments are register-local (C-layout == A-layout)
#pragma unroll
        for (int ks = 0; ks < 4; ks++) {
            uint32_t pa0 = packh2(sacc[2*ks    ][0], sacc[2*ks    ][1]);
            uint32_t pa1 = packh2(sacc[2*ks    ][2], sacc[2*ks    ][3]);
            uint32_t pa2 = packh2(sacc[2*ks + 1][0], sacc[2*ks + 1][1]);
            uint32_t pa3 = packh2(sacc[2*ks + 1][2], sacc[2*ks + 1][3]);
#pragma unroll
            for (int p = 0; p < 4; p++) {
                uint32_t b0, b1, b2, b3;
                ldsm4(b0, b1, b2, b3, vb + offB[p] + ks * 32);
                mma_f16(oacc[2*p    ], pa0, pa1, pa2, pa3, b0, b1);
                mma_f16(oacc[2*p + 1], pa0, pa1, pa2, pa3, b2, b3);
            }
        }
    }

    // Epilogue: normalize, write fp16 [B,S,D] (feeds O-projection)
    float i1 = 1.0f / l1, i2 = 1.0f / l2;
    const int row1 = q0 + mrow + r;
#pragma unroll
    for (int nt = 0; nt < 8; nt++) {
        int col = h * HS + nt * 8 + 2 * q;
        *(__half2*)&O[(size_t)(b * SEQ + row1) * DIM + col] =
            __floats2half2_rn(oacc[nt][0] * i1, oacc[nt][1] * i1);
        *(__half2*)&O[(size_t)(b * SEQ + row1 + 8) * DIM + col] =
            __floats2half2_rn(oacc[nt][2] * i2, oacc[nt][3] * i2);
    }
}

// ---------------------------------------------------------------------------
extern "C" void kernel_launch(void* const* d_in, const int* in_sizes, int n_in,
                              void* d_out, int out_size)
{
    const float* x  = (const float*)d_in[0];
    const float* Wq = (const float*)d_in[1];
    const float* bq = (const float*)d_in[2];
    const float* Wk = (const float*)d_in[3];
    const float* bk = (const float*)d_in[4];
    const float* Wv = (const float*)d_in[5];
    const float* bv = (const float*)d_in[6];
    const float* Wo = (const float*)d_in[7];
    const float* bo = (const float*)d_in[8];
    float* out = (float*)d_out;

    __half *Qp, *Kp, *Vp, *Ap, *Xp, *WTp;
    cudaGetSymbolAddress((void**)&Qp,  g_Qh);
    cudaGetSymbolAddress((void**)&Kp,  g_Kh);
    cudaGetSymbolAddress((void**)&Vp,  g_Vh);
    cudaGetSymbolAddress((void**)&Ap,  g_Ah);
    cudaGetSymbolAddress((void**)&Xp,  g_Xh);
    cudaGetSymbolAddress((void**)&WTp, g_WTh);

    const int GEMM_SMEM  = 4 * HTILEB;   // 40,960
    const int FLASH_SMEM = 4 * FKV;      // 36,864
    cudaFuncSetAttribute(gemm_h,  cudaFuncAttributeMaxDynamicSharedMemorySize, GEMM_SMEM);
    cudaFuncSetAttribute(flash_h, cudaFuncAttributeMaxDynamicSharedMemorySize, FLASH_SMEM);

    conv_x_h<<<(MTOT * DIM / 4 + 255) / 256, 256>>>(x, Xp, MTOT * DIM);
    transpose_w_h<<<dim3(DIM / 32, DIM / 32, 4), dim3(32, 8)>>>(Wq, Wk, Wv, Wo, WTp);

    // hs^-0.5 * log2(e) folded into Q (softmax runs in exp2 domain)
    const float qscale = 0.125f * 1.44269504088896340736f;

    dim3 gridQKV(3 * DIM / 128, MTOT / 128);   // (18, 64)
    gemm_h<<<gridQKV, 256, GEMM_SMEM>>>(Xp, WTp, bq, bk, bv, Qp, Kp, Vp, 1, qscale);

    dim3 gridF(SEQ / 128, HEADS, BATCH);       // (16, 12, 4)
    flash_h<<<gridF, 256, FLASH_SMEM>>>(Qp, Kp, Vp, Ap);

    dim3 gridO(DIM / 128, MTOT / 128);         // (6, 64)
    gemm_h<<<gridO, 256, GEMM_SMEM>>>(Ap, WTp + 3 * DIM * DIM, bo, bo, bo,
                                      out, Kp, Vp, 0, 1.0f);
}

// round 10
// speedup vs baseline: 8.1988x; 1.0166x over previous
#include <cuda_runtime.h>
#include <cuda_fp16.h>
#include <cstdint>
#include <math.h>

#define BATCH 4
#define SEQ   2048
#define DIM   768
#define HEADS 12
#define HS    64
#define MTOT  (BATCH*SEQ)
#define GK    DIM

// Scratch (allocation-free: __device__ globals), all fp16
static __device__ __half g_Qh[BATCH*HEADS*SEQ*HS];
static __device__ __half g_Kh[BATCH*HEADS*SEQ*HS];
static __device__ __half g_Vh[BATCH*HEADS*SEQ*HS];   // [B,H,hs,S] (transposed)
static __device__ __half g_Ah[MTOT*DIM];             // attention output, fp16
static __device__ __half g_Xh[MTOT*DIM];             // fp16 x
static __device__ __half g_WTh[4*DIM*DIM];           // fp16 W^T (N x K row-major)

// ---------------------------------------------------------------------------
// Helpers
// ---------------------------------------------------------------------------
__device__ __forceinline__ uint32_t s2u(const void* p) {
    uint32_t a;
    asm("{ .reg .u64 t; cvta.to.shared.u64 t, %1; cvt.u32.u64 %0, t; }"
        : "=r"(a) : "l"(p));
    return a;
}
__device__ __forceinline__ float ex2f(float x) {
    float y;
    asm("ex2.approx.ftz.f32 %0, %1;" : "=f"(y) : "f"(x));
    return y;
}
__device__ __forceinline__ uint32_t packh2(float lo, float hi) {
    __half2 h = __floats2half2_rn(lo, hi);
    return *(uint32_t*)&h;
}
__device__ __forceinline__ void cp16(uint32_t dst, const void* src) {
    asm volatile("cp.async.cg.shared.global [%0], [%1], 16;"
                 :: "r"(dst), "l"(src) : "memory");
}
#define CP_COMMIT asm volatile("cp.async.commit_group;" ::: "memory")
#define CP_WAIT0  asm volatile("cp.async.wait_group 0;" ::: "memory")

__device__ __forceinline__ void ldsm4(uint32_t& r0, uint32_t& r1, uint32_t& r2,
                                      uint32_t& r3, uint32_t a) {
    asm volatile("ldmatrix.sync.aligned.m8n8.x4.shared.b16 {%0,%1,%2,%3}, [%4];"
        : "=r"(r0), "=r"(r1), "=r"(r2), "=r"(r3) : "r"(a));
}

// D += A * B  (m16n8k16 f16, f32 accumulate)
__device__ __forceinline__ void mma_f16(float* d, uint32_t a0, uint32_t a1,
                                        uint32_t a2, uint32_t a3,
                                        uint32_t b0, uint32_t b1) {
    asm volatile(
        "mma.sync.aligned.m16n8k16.row.col.f32.f16.f16.f32 "
        "{%0,%1,%2,%3}, {%4,%5,%6,%7}, {%8,%9}, {%0,%1,%2,%3};"
        : "+f"(d[0]), "+f"(d[1]), "+f"(d[2]), "+f"(d[3])
        : "r"(a0), "r"(a1), "r"(a2), "r"(a3), "r"(b0), "r"(b1));
}

// ---------------------------------------------------------------------------
// Prep kernels: x -> fp16; W -> fp16 transposed (N x K)
// ---------------------------------------------------------------------------
__global__ void conv_x_h(const float* __restrict__ x, __half* __restrict__ y, int n) {
    int i = (blockIdx.x * blockDim.x + threadIdx.x) * 4;
    if (i < n) {
        float4 v = *(const float4*)&x[i];
        *(__half2*)&y[i]     = __floats2half2_rn(v.x, v.y);
        *(__half2*)&y[i + 2] = __floats2half2_rn(v.z, v.w);
    }
}

__global__ void transpose_w_h(const float* __restrict__ W0, const float* __restrict__ W1,
                              const float* __restrict__ W2, const float* __restrict__ W3,
                              __half* __restrict__ WT) {
    __shared__ float t[32][33];
    const float* W = (blockIdx.z == 0) ? W0 : (blockIdx.z == 1) ? W1
                   : (blockIdx.z == 2) ? W2 : W3;
    __half* O = WT + blockIdx.z * DIM * DIM;
    int k0 = blockIdx.y * 32, n0 = blockIdx.x * 32;
    for (int r = threadIdx.y; r < 32; r += 8)
        t[r][threadIdx.x] = W[(k0 + r) * DIM + n0 + threadIdx.x];
    __syncthreads();
    for (int r = threadIdx.y; r < 32; r += 8)
        O[(n0 + r) * DIM + k0 + threadIdx.x] = __float2half_rn(t[threadIdx.x][r]);
}

// ---------------------------------------------------------------------------
// fp16 warp-MMA GEMM (unchanged from R8)
// ---------------------------------------------------------------------------
#define HSTB   80           // smem row stride bytes (40 halves)
#define HTILEB (128*HSTB)   // 10240

__global__ __launch_bounds__(256, 2)
void gemm_h(const __half* __restrict__ A, const __half* __restrict__ Bt,
            const float* __restrict__ bias0, const float* __restrict__ bias1,
            const float* __restrict__ bias2,
            void* __restrict__ C0v, __half* __restrict__ C1, __half* __restrict__ C2,
            int fused, float qscale)
{
    extern __shared__ __half smh[];
    const int tid = threadIdx.x;
    const int wid = tid >> 5, lane = tid & 31;
    const int wm = wid & 3, wn = wid >> 2;
    const int r = lane >> 2, q = lane & 3;
    const int m0 = blockIdx.y * 128;
    const uint32_t sbase = s2u(smh);

    const int lrA = (lane & 7) + ((lane >> 3) & 1) * 8;
    const int loA = ((lane >> 4) & 1) * 16;
    const int lrB = (lane & 7) + ((lane >> 4) & 1) * 8;
    const int loB = ((lane >> 3) & 1) * 16;
    uint32_t offA[2], offB[4];
#pragma unroll
    for (int mt = 0; mt < 2; mt++)
        offA[mt] = (uint32_t)((wm * 32 + mt * 16 + lrA) * HSTB + loA);
#pragma unroll
    for (int p = 0; p < 4; p++)
        offB[p] = (uint32_t)((wn * 64 + p * 16 + lrB) * HSTB + loB);

    float acc[2][8][4];
#pragma unroll
    for (int mt = 0; mt < 2; mt++)
#pragma unroll
        for (int nt = 0; nt < 8; nt++)
#pragma unroll
            for (int j = 0; j < 4; j++) acc[mt][nt][j] = 0.f;

    const int btrow0 = blockIdx.x * 128;
    auto load_tiles = [&](int kc, int buf) {
        uint32_t ab = sbase + (uint32_t)buf * 2u * HTILEB;
        uint32_t bb = ab + HTILEB;
#pragma unroll
        for (int i = 0; i < 2; i++) {
            int e = tid + i * 256;
            int row = e >> 2, seg = e & 3;
            cp16(ab + row * HSTB + seg * 16, A  + (m0 + row) * GK + kc + seg * 8);
            cp16(bb + row * HSTB + seg * 16, Bt + (btrow0 + row) * GK + kc + seg * 8);
        }
    };

    load_tiles(0, 0);
    CP_COMMIT;

    const int NIT = GK / 32;   // 24
    for (int it = 0; it < NIT; it++) {
        CP_WAIT0;
        __syncthreads();
        if (it + 1 < NIT) { load_tiles((it + 1) * 32, (it + 1) & 1); CP_COMMIT; }

        const uint32_t baseA = sbase + (uint32_t)(it & 1) * 2u * HTILEB;
        const uint32_t baseB = baseA + HTILEB;
#pragma unroll
        for (int ks = 0; ks < 2; ks++) {
            uint32_t a[2][4];
            ldsm4(a[0][0], a[0][1], a[0][2], a[0][3], baseA + offA[0] + ks * 32);
            ldsm4(a[1][0], a[1][1], a[1][2], a[1][3], baseA + offA[1] + ks * 32);
#pragma unroll
            for (int p = 0; p < 4; p++) {
                uint32_t b0, b1, b2, b3;
                ldsm4(b0, b1, b2, b3, baseB + offB[p] + ks * 32);
                mma_f16(acc[0][2*p    ], a[0][0], a[0][1], a[0][2], a[0][3], b0, b1);
                mma_f16(acc[1][2*p    ], a[1][0], a[1][1], a[1][2], a[1][3], b0, b1);
                mma_f16(acc[0][2*p + 1], a[0][0], a[0][1], a[0][2], a[0][3], b2, b3);
                mma_f16(acc[1][2*p + 1], a[1][0], a[1][1], a[1][2], a[1][3], b2, b3);
            }
        }
    }

    int which = 0, nloc0 = blockIdx.x * 128;
    const float* bias = bias0;
    float scale = 1.f;
    if (fused) {
        which = blockIdx.x / 6;
        nloc0 = (blockIdx.x % 6) * 128;
        bias  = (which == 0) ? bias0 : (which == 1) ? bias1 : bias2;
        scale = (which == 0) ? qscale : 1.f;
    }

#pragma unroll
    for (int mt = 0; mt < 2; mt++) {
        int row = m0 + wm * 32 + mt * 16 + r;
#pragma unroll
        for (int nt = 0; nt < 8; nt++) {
            int col = nloc0 + wn * 64 + nt * 8 + 2 * q;
            float b0v = bias[col], b1v = bias[col + 1];
            float v0 = (acc[mt][nt][0] + b0v) * scale;
            float v1 = (acc[mt][nt][1] + b1v) * scale;
            float v2 = (acc[mt][nt][2] + b0v) * scale;
            float v3 = (acc[mt][nt][3] + b1v) * scale;
            if (!fused) {
                float* C0 = (float*)C0v;
                *(float2*)&C0[row * DIM + col]       = make_float2(v0, v1);
                *(float2*)&C0[(row + 8) * DIM + col] = make_float2(v2, v3);
            } else {
                int b = row >> 11;
                int h = col >> 6, d = col & 63;
                int s1 = row & 2047, s2 = s1 + 8;
                if (which < 2) {
                    __half* Cc = which ? C1 : (__half*)C0v;
                    __half* base = Cc + ((size_t)(b * HEADS + h) * SEQ) * HS + d;
                    *(__half2*)&base[s1 * HS] = __floats2half2_rn(v0, v1);
                    *(__half2*)&base[s2 * HS] = __floats2half2_rn(v2, v3);
                } else {
                    __half* base = C2 + ((size_t)(b * HEADS + h) * HS + d) * SEQ;
                    base[s1]       = __float2half_rn(v0);
                    base[SEQ + s1] = __float2half_rn(v1);
                    base[s2]       = __float2half_rn(v2);
                    base[SEQ + s2] = __float2half_rn(v3);
                }
            }
        }
    }
}

// ---------------------------------------------------------------------------
// Flash attention fp16: 4 warps x 32 q-rows (2 M-frags/warp), 128 threads.
// Every K/V B-fragment feeds 2x the MMAs -> crossbar traffic per q-row halves.
// FA2 register-local P (no P smem). 64-key tiles, cp.async double buffer.
// smem: Ks[2][64*72h] + Vs[2][64*72h] = 36,864 B; Q staged via K region once.
// ---------------------------------------------------------------------------
#define FH   144            // bytes per row (72 halves)
#define FKV  (64*FH)        // 9216

__global__ __launch_bounds__(128)
void flash_h(const __half* __restrict__ Q, const __half* __restrict__ K,
             const __half* __restrict__ V, __half* __restrict__ O)
{
    extern __shared__ __half fs[];

    const int tid = threadIdx.x;
    const int wid = tid >> 5, lane = tid & 31;
    const int r = lane >> 2, q = lane & 3;
    const int mrow = wid * 32;
    const int q0 = blockIdx.x * 128, h = blockIdx.y, b = blockIdx.z;

    const __half* Qg = Q + ((size_t)(b * HEADS + h) * SEQ + q0) * HS;
    const __half* Kg = K + ((size_t)(b * HEADS + h) * SEQ) * HS;
    const __half* Vg = V + ((size_t)(b * HEADS + h) * HS) * SEQ;

    const uint32_t kbase = s2u(fs);
    const uint32_t vbase = kbase + 2 * FKV;

    const int lrA = (lane & 7) + ((lane >> 3) & 1) * 8;
    const int loA = ((lane >> 4) & 1) * 16;
    const int lrB = (lane & 7) + ((lane >> 4) & 1) * 8;
    const int loB = ((lane >> 3) & 1) * 16;
    uint32_t offB[4];
#pragma unroll
    for (int p = 0; p < 4; p++)
        offB[p] = (uint32_t)((p * 16 + lrB) * FH + loB);

    // ---- Stage Q (128 x 64 halves) through the K-buffer region ----
#pragma unroll
    for (int i = 0; i < 8; i++) {
        int e = tid + i * 128;
        int row = e >> 3, seg = e & 7;
        *(uint4*)((char*)fs + row * FH + seg * 16) =
            *(const uint4*)(Qg + row * HS + seg * 8);
    }
    __syncthreads();
    uint32_t qf[2][4][4];
#pragma unroll
    for (int mt = 0; mt < 2; mt++) {
        const uint32_t offQ = (uint32_t)((mrow + mt * 16 + lrA) * FH + loA);
#pragma unroll
        for (int ks = 0; ks < 4; ks++)
            ldsm4(qf[mt][ks][0], qf[mt][ks][1], qf[mt][ks][2], qf[mt][ks][3],
                  kbase + offQ + ks * 32);
    }
    __syncthreads();   // all qf reads done before cp.async overwrites region

    auto load_kv = [&](int t, int buf) {
        uint32_t kb = kbase + (uint32_t)buf * FKV;
        uint32_t vb = vbase + (uint32_t)buf * FKV;
#pragma unroll
        for (int i = 0; i < 4; i++) {
            int e = tid + i * 128;
            int row = e >> 3, seg = e & 7;
            cp16(kb + row * FH + seg * 16, Kg + (t * 64 + row) * HS + seg * 8);
            cp16(vb + row * FH + seg * 16, Vg + row * SEQ + t * 64 + seg * 8);
        }
    };

    load_kv(0, 0);
    CP_COMMIT;

    float mx[2][2], ls[2][2];
#pragma unroll
    for (int mt = 0; mt < 2; mt++) {
        mx[mt][0] = mx[mt][1] = -1e30f;
        ls[mt][0] = ls[mt][1] = 0.f;
    }
    float oacc[2][8][4];
#pragma unroll
    for (int mt = 0; mt < 2; mt++)
#pragma unroll
        for (int nt = 0; nt < 8; nt++)
#pragma unroll
            for (int j = 0; j < 4; j++) oacc[mt][nt][j] = 0.f;

    const int NT = SEQ / 64;  // 32
    for (int t = 0; t < NT; t++) {
        CP_WAIT0;
        __syncthreads();
        if (t + 1 < NT) { load_kv(t + 1, (t + 1) & 1); CP_COMMIT; }

        const uint32_t kb = kbase + (uint32_t)(t & 1) * FKV;
        const uint32_t vb = vbase + (uint32_t)(t & 1) * FKV;

        // S = Q @ K^T  (4 k16-steps; each B-frag feeds both M-frags)
        float sacc[2][8][4];
#pragma unroll
        for (int mt = 0; mt < 2; mt++)
#pragma unroll
            for (int nt = 0; nt < 8; nt++)
#pragma unroll
                for (int j = 0; j < 4; j++) sacc[mt][nt][j] = 0.f;
#pragma unroll
        for (int ks = 0; ks < 4; ks++) {
#pragma unroll
            for (int p = 0; p < 4; p++) {
                uint32_t b0, b1, b2, b3;
                ldsm4(b0, b1, b2, b3, kb + offB[p] + ks * 32);
                mma_f16(sacc[0][2*p    ], qf[0][ks][0], qf[0][ks][1], qf[0][ks][2], qf[0][ks][3], b0, b1);
                mma_f16(sacc[1][2*p    ], qf[1][ks][0], qf[1][ks][1], qf[1][ks][2], qf[1][ks][3], b0, b1);
                mma_f16(sacc[0][2*p + 1], qf[0][ks][0], qf[0][ks][1], qf[0][ks][2], qf[0][ks][3], b2, b3);
                mma_f16(sacc[1][2*p + 1], qf[1][ks][0], qf[1][ks][1], qf[1][ks][2], qf[1][ks][3], b2, b3);
            }
        }

        // Online softmax per M-frag (exp2 domain)
#pragma unroll
        for (int mt = 0; mt < 2; mt++) {
            float mt1 = -1e30f, mt2 = -1e30f;
#pragma unroll
            for (int nt = 0; nt < 8; nt++) {
                mt1 = fmaxf(mt1, fmaxf(sacc[mt][nt][0], sacc[mt][nt][1]));
                mt2 = fmaxf(mt2, fmaxf(sacc[mt][nt][2], sacc[mt][nt][3]));
            }
            mt1 = fmaxf(mt1, __shfl_xor_sync(0xffffffffu, mt1, 1));
            mt1 = fmaxf(mt1, __shfl_xor_sync(0xffffffffu, mt1, 2));
            mt2 = fmaxf(mt2, __shfl_xor_sync(0xffffffffu, mt2, 1));
            mt2 = fmaxf(mt2, __shfl_xor_sync(0xffffffffu, mt2, 2));
            float mn1 = fmaxf(mx[mt][0], mt1), mn2 = fmaxf(mx[mt][1], mt2);
            float c1 = ex2f(mx[mt][0] - mn1), c2 = ex2f(mx[mt][1] - mn2);
            mx[mt][0] = mn1; mx[mt][1] = mn2;
            float rs1 = 0.f, rs2 = 0.f;
#pragma unroll
            for (int nt = 0; nt < 8; nt++) {
                sacc[mt][nt][0] = ex2f(sacc[mt][nt][0] - mn1); rs1 += sacc[mt][nt][0];
                sacc[mt][nt][1] = ex2f(sacc[mt][nt][1] - mn1); rs1 += sacc[mt][nt][1];
                sacc[mt][nt][2] = ex2f(sacc[mt][nt][2] - mn2); rs2 += sacc[mt][nt][2];
                sacc[mt][nt][3] = ex2f(sacc[mt][nt][3] - mn2); rs2 += sacc[mt][nt][3];
            }
            rs1 += __shfl_xor_sync(0xffffffffu, rs1, 1);
            rs1 += __shfl_xor_sync(0xffffffffu, rs1, 2);
            rs2 += __shfl_xor_sync(0xffffffffu, rs2, 1);
            rs2 += __shfl_xor_sync(0xffffffffu, rs2, 2);
            ls[mt][0] = ls[mt][0] * c1 + rs1;
            ls[mt][1] = ls[mt][1] * c2 + rs2;
#pragma unroll
            for (int nt = 0; nt < 8; nt++) {
                oacc[mt][nt][0] *= c1; oacc[mt][nt][1] *= c1;
                oacc[mt][nt][2] *= c2; oacc[mt][nt][3] *= c2;
            }
        }

        // O += P @ V : register-local P A-frags, each V B-frag feeds both M-frags
#pragma unroll
        for (int ks = 0; ks < 4; ks++) {
            uint32_t pa[2][4];
#pragma unroll
            for (int mt = 0; mt < 2; mt++) {
                pa[mt][0] = packh2(sacc[mt][2*ks    ][0], sacc[mt][2*ks    ][1]);
                pa[mt][1] = packh2(sacc[mt][2*ks    ][2], sacc[mt][2*ks    ][3]);
                pa[mt][2] = packh2(sacc[mt][2*ks + 1][0], sacc[mt][2*ks + 1][1]);
                pa[mt][3] = packh2(sacc[mt][2*ks + 1][2], sacc[mt][2*ks + 1][3]);
            }
#pragma unroll
            for (int p = 0; p < 4; p++) {
                uint32_t b0, b1, b2, b3;
                ldsm4(b0, b1, b2, b3, vb + offB[p] + ks * 32);
                mma_f16(oacc[0][2*p    ], pa[0][0], pa[0][1], pa[0][2], pa[0][3], b0, b1);
                mma_f16(oacc[1][2*p    ], pa[1][0], pa[1][1], pa[1][2], pa[1][3], b0, b1);
                mma_f16(oacc[0][2*p + 1], pa[0][0], pa[0][1], pa[0][2], pa[0][3], b2, b3);
                mma_f16(oacc[1][2*p + 1], pa[1][0], pa[1][1], pa[1][2], pa[1][3], b2, b3);
            }
        }
    }

    // Epilogue: normalize, write fp16 [B,S,D] (feeds O-projection)
#pragma unroll
    for (int mt = 0; mt < 2; mt++) {
        float i1 = 1.0f / ls[mt][0], i2 = 1.0f / ls[mt][1];
        const int row1 = q0 + mrow + mt * 16 + r;
#pragma unroll
        for (int nt = 0; nt < 8; nt++) {
            int col = h * HS + nt * 8 + 2 * q;
            *(__half2*)&O[(size_t)(b * SEQ + row1) * DIM + col] =
                __floats2half2_rn(oacc[mt][nt][0] * i1, oacc[mt][nt][1] * i1);
            *(__half2*)&O[(size_t)(b * SEQ + row1 + 8) * DIM + col] =
                __floats2half2_rn(oacc[mt][nt][2] * i2, oacc[mt][nt][3] * i2);
        }
    }
}

// ---------------------------------------------------------------------------
extern "C" void kernel_launch(void* const* d_in, const int* in_sizes, int n_in,
                              void* d_out, int out_size)
{
    const float* x  = (const float*)d_in[0];
    const float* Wq = (const float*)d_in[1];
    const float* bq = (const float*)d_in[2];
    const float* Wk = (const float*)d_in[3];
    const float* bk = (const float*)d_in[4];
    const float* Wv = (const float*)d_in[5];
    const float* bv = (const float*)d_in[6];
    const float* Wo = (const float*)d_in[7];
    const float* bo = (const float*)d_in[8];
    float* out = (float*)d_out;

    __half *Qp, *Kp, *Vp, *Ap, *Xp, *WTp;
    cudaGetSymbolAddress((void**)&Qp,  g_Qh);
    cudaGetSymbolAddress((void**)&Kp,  g_Kh);
    cudaGetSymbolAddress((void**)&Vp,  g_Vh);
    cudaGetSymbolAddress((void**)&Ap,  g_Ah);
    cudaGetSymbolAddress((void**)&Xp,  g_Xh);
    cudaGetSymbolAddress((void**)&WTp, g_WTh);

    const int GEMM_SMEM  = 4 * HTILEB;   // 40,960
    const int FLASH_SMEM = 4 * FKV;      // 36,864
    cudaFuncSetAttribute(gemm_h,  cudaFuncAttributeMaxDynamicSharedMemorySize, GEMM_SMEM);
    cudaFuncSetAttribute(flash_h, cudaFuncAttributeMaxDynamicSharedMemorySize, FLASH_SMEM);

    conv_x_h<<<(MTOT * DIM / 4 + 255) / 256, 256>>>(x, Xp, MTOT * DIM);
    transpose_w_h<<<dim3(DIM / 32, DIM / 32, 4), dim3(32, 8)>>>(Wq, Wk, Wv, Wo, WTp);

    // hs^-0.5 * log2(e) folded into Q (softmax runs in exp2 domain)
    const float qscale = 0.125f * 1.44269504088896340736f;

    dim3 gridQKV(3 * DIM / 128, MTOT / 128);   // (18, 64)
    gemm_h<<<gridQKV, 256, GEMM_SMEM>>>(Xp, WTp, bq, bk, bv, Qp, Kp, Vp, 1, qscale);

    dim3 gridF(SEQ / 128, HEADS, BATCH);       // (16, 12, 4)
    flash_h<<<gridF, 128, FLASH_SMEM>>>(Qp, Kp, Vp, Ap);

    dim3 gridO(DIM / 128, MTOT / 128);         // (6, 64)
    gemm_h<<<gridO, 256, GEMM_SMEM>>>(Ap, WTp + 3 * DIM * DIM, bo, bo, bo,
                                      out, Kp, Vp, 0, 1.0f);
}

// round 12
// speedup vs baseline: 8.2527x; 1.0066x over previous
#include <cuda_runtime.h>
#include <cuda_fp16.h>
#include <cstdint>
#include <math.h>

#define BATCH 4
#define SEQ   2048
#define DIM   768
#define HEADS 12
#define HS    64
#define MTOT  (BATCH*SEQ)
#define GK    DIM

// Scratch (allocation-free: __device__ globals), all fp16
static __device__ __half g_Qh[BATCH*HEADS*SEQ*HS];
static __device__ __half g_Kh[BATCH*HEADS*SEQ*HS];
static __device__ __half g_Vh[BATCH*HEADS*SEQ*HS];   // [B,H,hs,S] (transposed)
static __device__ __half g_Ah[MTOT*DIM];             // attention output, fp16
static __device__ __half g_Xh[MTOT*DIM];             // fp16 x
static __device__ __half g_WTh[4*DIM*DIM];           // fp16 W^T (N x K row-major)

// ---------------------------------------------------------------------------
// Helpers
// ---------------------------------------------------------------------------
__device__ __forceinline__ uint32_t s2u(const void* p) {
    uint32_t a;
    asm("{ .reg .u64 t; cvta.to.shared.u64 t, %1; cvt.u32.u64 %0, t; }"
        : "=r"(a) : "l"(p));
    return a;
}
__device__ __forceinline__ float ex2f(float x) {
    float y;
    asm("ex2.approx.ftz.f32 %0, %1;" : "=f"(y) : "f"(x));
    return y;
}
__device__ __forceinline__ uint32_t packh2(float lo, float hi) {
    __half2 h = __floats2half2_rn(lo, hi);
    return *(uint32_t*)&h;
}
__device__ __forceinline__ void cp16(uint32_t dst, const void* src) {
    asm volatile("cp.async.cg.shared.global [%0], [%1], 16;"
                 :: "r"(dst), "l"(src) : "memory");
}
#define CP_COMMIT asm volatile("cp.async.commit_group;" ::: "memory")
#define CP_WAIT0  asm volatile("cp.async.wait_group 0;" ::: "memory")

__device__ __forceinline__ void ldsm4(uint32_t& r0, uint32_t& r1, uint32_t& r2,
                                      uint32_t& r3, uint32_t a) {
    asm volatile("ldmatrix.sync.aligned.m8n8.x4.shared.b16 {%0,%1,%2,%3}, [%4];"
        : "=r"(r0), "=r"(r1), "=r"(r2), "=r"(r3) : "r"(a));
}

// D += A * B  (m16n8k16 f16, f32 accumulate)
__device__ __forceinline__ void mma_f16(float* d, uint32_t a0, uint32_t a1,
                                        uint32_t a2, uint32_t a3,
                                        uint32_t b0, uint32_t b1) {
    asm volatile(
        "mma.sync.aligned.m16n8k16.row.col.f32.f16.f16.f32 "
        "{%0,%1,%2,%3}, {%4,%5,%6,%7}, {%8,%9}, {%0,%1,%2,%3};"
        : "+f"(d[0]), "+f"(d[1]), "+f"(d[2]), "+f"(d[3])
        : "r"(a0), "r"(a1), "r"(a2), "r"(a3), "r"(b0), "r"(b1));
}

// ---------------------------------------------------------------------------
// Prep kernels: x -> fp16; W -> fp16 transposed (N x K)
// ---------------------------------------------------------------------------
__global__ void conv_x_h(const float* __restrict__ x, __half* __restrict__ y, int n) {
    int i = (blockIdx.x * blockDim.x + threadIdx.x) * 4;
    if (i < n) {
        float4 v = *(const float4*)&x[i];
        *(__half2*)&y[i]     = __floats2half2_rn(v.x, v.y);
        *(__half2*)&y[i + 2] = __floats2half2_rn(v.z, v.w);
    }
}

__global__ void transpose_w_h(const float* __restrict__ W0, const float* __restrict__ W1,
                              const float* __restrict__ W2, const float* __restrict__ W3,
                              __half* __restrict__ WT) {
    __shared__ float t[32][33];
    const float* W = (blockIdx.z == 0) ? W0 : (blockIdx.z == 1) ? W1
                   : (blockIdx.z == 2) ? W2 : W3;
    __half* O = WT + blockIdx.z * DIM * DIM;
    int k0 = blockIdx.y * 32, n0 = blockIdx.x * 32;
    for (int r = threadIdx.y; r < 32; r += 8)
        t[r][threadIdx.x] = W[(k0 + r) * DIM + n0 + threadIdx.x];
    __syncthreads();
    for (int r = threadIdx.y; r < 32; r += 8)
        O[(n0 + r) * DIM + k0 + threadIdx.x] = __float2half_rn(t[threadIdx.x][r]);
}

// ---------------------------------------------------------------------------
// fp16 warp-MMA GEMM (unchanged)
// ---------------------------------------------------------------------------
#define HSTB   80           // smem row stride bytes (40 halves)
#define HTILEB (128*HSTB)   // 10240

__global__ __launch_bounds__(256, 2)
void gemm_h(const __half* __restrict__ A, const __half* __restrict__ Bt,
            const float* __restrict__ bias0, const float* __restrict__ bias1,
            const float* __restrict__ bias2,
            void* __restrict__ C0v, __half* __restrict__ C1, __half* __restrict__ C2,
            int fused, float qscale)
{
    extern __shared__ __half smh[];
    const int tid = threadIdx.x;
    const int wid = tid >> 5, lane = tid & 31;
    const int wm = wid & 3, wn = wid >> 2;
    const int r = lane >> 2, q = lane & 3;
    const int m0 = blockIdx.y * 128;
    const uint32_t sbase = s2u(smh);

    const int lrA = (lane & 7) + ((lane >> 3) & 1) * 8;
    const int loA = ((lane >> 4) & 1) * 16;
    const int lrB = (lane & 7) + ((lane >> 4) & 1) * 8;
    const int loB = ((lane >> 3) & 1) * 16;
    uint32_t offA[2], offB[4];
#pragma unroll
    for (int mt = 0; mt < 2; mt++)
        offA[mt] = (uint32_t)((wm * 32 + mt * 16 + lrA) * HSTB + loA);
#pragma unroll
    for (int p = 0; p < 4; p++)
        offB[p] = (uint32_t)((wn * 64 + p * 16 + lrB) * HSTB + loB);

    float acc[2][8][4];
#pragma unroll
    for (int mt = 0; mt < 2; mt++)
#pragma unroll
        for (int nt = 0; nt < 8; nt++)
#pragma unroll
            for (int j = 0; j < 4; j++) acc[mt][nt][j] = 0.f;

    const int btrow0 = blockIdx.x * 128;
    auto load_tiles = [&](int kc, int buf) {
        uint32_t ab = sbase + (uint32_t)buf * 2u * HTILEB;
        uint32_t bb = ab + HTILEB;
#pragma unroll
        for (int i = 0; i < 2; i++) {
            int e = tid + i * 256;
            int row = e >> 2, seg = e & 3;
            cp16(ab + row * HSTB + seg * 16, A  + (m0 + row) * GK + kc + seg * 8);
            cp16(bb + row * HSTB + seg * 16, Bt + (btrow0 + row) * GK + kc + seg * 8);
        }
    };

    load_tiles(0, 0);
    CP_COMMIT;

    const int NIT = GK / 32;   // 24
    for (int it = 0; it < NIT; it++) {
        CP_WAIT0;
        __syncthreads();
        if (it + 1 < NIT) { load_tiles((it + 1) * 32, (it + 1) & 1); CP_COMMIT; }

        const uint32_t baseA = sbase + (uint32_t)(it & 1) * 2u * HTILEB;
        const uint32_t baseB = baseA + HTILEB;
#pragma unroll
        for (int ks = 0; ks < 2; ks++) {
            uint32_t a[2][4];
            ldsm4(a[0][0], a[0][1], a[0][2], a[0][3], baseA + offA[0] + ks * 32);
            ldsm4(a[1][0], a[1][1], a[1][2], a[1][3], baseA + offA[1] + ks * 32);
#pragma unroll
            for (int p = 0; p < 4; p++) {
                uint32_t b0, b1, b2, b3;
                ldsm4(b0, b1, b2, b3, baseB + offB[p] + ks * 32);
                mma_f16(acc[0][2*p    ], a[0][0], a[0][1], a[0][2], a[0][3], b0, b1);
                mma_f16(acc[1][2*p    ], a[1][0], a[1][1], a[1][2], a[1][3], b0, b1);
                mma_f16(acc[0][2*p + 1], a[0][0], a[0][1], a[0][2], a[0][3], b2, b3);
                mma_f16(acc[1][2*p + 1], a[1][0], a[1][1], a[1][2], a[1][3], b2, b3);
            }
        }
    }

    int which = 0, nloc0 = blockIdx.x * 128;
    const float* bias = bias0;
    float scale = 1.f;
    if (fused) {
        which = blockIdx.x / 6;
        nloc0 = (blockIdx.x % 6) * 128;
        bias  = (which == 0) ? bias0 : (which == 1) ? bias1 : bias2;
        scale = (which == 0) ? qscale : 1.f;
    }

#pragma unroll
    for (int mt = 0; mt < 2; mt++) {
        int row = m0 + wm * 32 + mt * 16 + r;
#pragma unroll
        for (int nt = 0; nt < 8; nt++) {
            int col = nloc0 + wn * 64 + nt * 8 + 2 * q;
            float b0v = bias[col], b1v = bias[col + 1];
            float v0 = (acc[mt][nt][0] + b0v) * scale;
            float v1 = (acc[mt][nt][1] + b1v) * scale;
            float v2 = (acc[mt][nt][2] + b0v) * scale;
            float v3 = (acc[mt][nt][3] + b1v) * scale;
            if (!fused) {
                float* C0 = (float*)C0v;
                *(float2*)&C0[row * DIM + col]       = make_float2(v0, v1);
                *(float2*)&C0[(row + 8) * DIM + col] = make_float2(v2, v3);
            } else {
                int b = row >> 11;
                int h = col >> 6, d = col & 63;
                int s1 = row & 2047, s2 = s1 + 8;
                if (which < 2) {
                    __half* Cc = which ? C1 : (__half*)C0v;
                    __half* base = Cc + ((size_t)(b * HEADS + h) * SEQ) * HS + d;
                    *(__half2*)&base[s1 * HS] = __floats2half2_rn(v0, v1);
                    *(__half2*)&base[s2 * HS] = __floats2half2_rn(v2, v3);
                } else {
                    __half* base = C2 + ((size_t)(b * HEADS + h) * HS + d) * SEQ;
                    base[s1]       = __float2half_rn(v0);
                    base[SEQ + s1] = __float2half_rn(v1);
                    base[s2]       = __float2half_rn(v2);
                    base[SEQ + s2] = __float2half_rn(v3);
                }
            }
        }
    }
}

// ---------------------------------------------------------------------------
// Flash attention fp16: 4 warps x 32 q-rows (2 M-frags/warp), 128 threads.
// Tile body is software-pipelined across M-frags to overlap softmax ALU with
// MMA drain:  S(0) -> S(1) -> softmax(0) -> PV(0) -> softmax(1) -> PV(1).
// K/V B-frags are re-loaded per M-frag pass (crossbar has headroom).
// FA2 register-local P. smem: Ks[2]+Vs[2] = 36,864 B; Q staged via K region.
// ---------------------------------------------------------------------------
#define FH   144            // bytes per row (72 halves)
#define FKV  (64*FH)        // 9216

__global__ __launch_bounds__(128)
void flash_h(const __half* __restrict__ Q, const __half* __restrict__ K,
             const __half* __restrict__ V, __half* __restrict__ O)
{
    extern __shared__ __half fs[];

    const int tid = threadIdx.x;
    const int wid = tid >> 5, lane = tid & 31;
    const int r = lane >> 2, q = lane & 3;
    const int mrow = wid * 32;
    const int q0 = blockIdx.x * 128, h = blockIdx.y, b = blockIdx.z;

    const __half* Qg = Q + ((size_t)(b * HEADS + h) * SEQ + q0) * HS;
    const __half* Kg = K + ((size_t)(b * HEADS + h) * SEQ) * HS;
    const __half* Vg = V + ((size_t)(b * HEADS + h) * HS) * SEQ;

    const uint32_t kbase = s2u(fs);
    const uint32_t vbase = kbase + 2 * FKV;

    const int lrA = (lane & 7) + ((lane >> 3) & 1) * 8;
    const int loA = ((lane >> 4) & 1) * 16;
    const int lrB = (lane & 7) + ((lane >> 4) & 1) * 8;
    const int loB = ((lane >> 3) & 1) * 16;
    uint32_t offB[4];
#pragma unroll
    for (int p = 0; p < 4; p++)
        offB[p] = (uint32_t)((p * 16 + lrB) * FH + loB);

    // ---- Stage Q (128 x 64 halves) through the K-buffer region ----
#pragma unroll
    for (int i = 0; i < 8; i++) {
        int e = tid + i * 128;
        int row = e >> 3, seg = e & 7;
        *(uint4*)((char*)fs + row * FH + seg * 16) =
            *(const uint4*)(Qg + row * HS + seg * 8);
    }
    __syncthreads();
    uint32_t qf[2][4][4];
#pragma unroll
    for (int mt = 0; mt < 2; mt++) {
        const uint32_t offQ = (uint32_t)((mrow + mt * 16 + lrA) * FH + loA);
#pragma unroll
        for (int ks = 0; ks < 4; ks++)
            ldsm4(qf[mt][ks][0], qf[mt][ks][1], qf[mt][ks][2], qf[mt][ks][3],
                  kbase + offQ + ks * 32);
    }
    __syncthreads();   // all qf reads done before cp.async overwrites region

    auto load_kv = [&](int t, int buf) {
        uint32_t kb = kbase + (uint32_t)buf * FKV;
        uint32_t vb = vbase + (uint32_t)buf * FKV;
#pragma unroll
        for (int i = 0; i < 4; i++) {
            int e = tid + i * 128;
            int row = e >> 3, seg = e & 7;
            cp16(kb + row * FH + seg * 16, Kg + (t * 64 + row) * HS + seg * 8);
            cp16(vb + row * FH + seg * 16, Vg + row * SEQ + t * 64 + seg * 8);
        }
    };

    load_kv(0, 0);
    CP_COMMIT;

    float mx[2][2], ls[2][2];
#pragma unroll
    for (int mt = 0; mt < 2; mt++) {
        mx[mt][0] = mx[mt][1] = -1e30f;
        ls[mt][0] = ls[mt][1] = 0.f;
    }
    float oacc[2][8][4];
#pragma unroll
    for (int mt = 0; mt < 2; mt++)
#pragma unroll
        for (int nt = 0; nt < 8; nt++)
#pragma unroll
            for (int j = 0; j < 4; j++) oacc[mt][nt][j] = 0.f;

    const int NT = SEQ / 64;  // 32
    for (int t = 0; t < NT; t++) {
        CP_WAIT0;
        __syncthreads();
        if (t + 1 < NT) { load_kv(t + 1, (t + 1) & 1); CP_COMMIT; }

        const uint32_t kb = kbase + (uint32_t)(t & 1) * FKV;
        const uint32_t vb = vbase + (uint32_t)(t & 1) * FKV;

        float sacc[2][8][4];
#pragma unroll
        for (int mt = 0; mt < 2; mt++)
#pragma unroll
            for (int nt = 0; nt < 8; nt++)
#pragma unroll
                for (int j = 0; j < 4; j++) sacc[mt][nt][j] = 0.f;

        // ---- S(mt0), S(mt1): separate passes, each with its own K ldsm ----
#pragma unroll
        for (int mt = 0; mt < 2; mt++) {
#pragma unroll
            for (int ks = 0; ks < 4; ks++) {
#pragma unroll
                for (int p = 0; p < 4; p++) {
                    uint32_t b0, b1, b2, b3;
                    ldsm4(b0, b1, b2, b3, kb + offB[p] + ks * 32);
                    mma_f16(sacc[mt][2*p    ], qf[mt][ks][0], qf[mt][ks][1],
                            qf[mt][ks][2], qf[mt][ks][3], b0, b1);
                    mma_f16(sacc[mt][2*p + 1], qf[mt][ks][0], qf[mt][ks][1],
                            qf[mt][ks][2], qf[mt][ks][3], b2, b3);
                }
            }
        }

        // ---- softmax(mt) then PV(mt): softmax(1) overlaps PV(0) drain ----
#pragma unroll
        for (int mt = 0; mt < 2; mt++) {
            float mt1 = -1e30f, mt2 = -1e30f;
#pragma unroll
            for (int nt = 0; nt < 8; nt++) {
                mt1 = fmaxf(mt1, fmaxf(sacc[mt][nt][0], sacc[mt][nt][1]));
                mt2 = fmaxf(mt2, fmaxf(sacc[mt][nt][2], sacc[mt][nt][3]));
            }
            mt1 = fmaxf(mt1, __shfl_xor_sync(0xffffffffu, mt1, 1));
            mt1 = fmaxf(mt1, __shfl_xor_sync(0xffffffffu, mt1, 2));
            mt2 = fmaxf(mt2, __shfl_xor_sync(0xffffffffu, mt2, 1));
            mt2 = fmaxf(mt2, __shfl_xor_sync(0xffffffffu, mt2, 2));
            float mn1 = fmaxf(mx[mt][0], mt1), mn2 = fmaxf(mx[mt][1], mt2);
            float c1 = ex2f(mx[mt][0] - mn1), c2 = ex2f(mx[mt][1] - mn2);
            mx[mt][0] = mn1; mx[mt][1] = mn2;
            float rs1 = 0.f, rs2 = 0.f;
#pragma unroll
            for (int nt = 0; nt < 8; nt++) {
                sacc[mt][nt][0] = ex2f(sacc[mt][nt][0] - mn1); rs1 += sacc[mt][nt][0];
                sacc[mt][nt][1] = ex2f(sacc[mt][nt][1] - mn1); rs1 += sacc[mt][nt][1];
                sacc[mt][nt][2] = ex2f(sacc[mt][nt][2] - mn2); rs2 += sacc[mt][nt][2];
                sacc[mt][nt][3] = ex2f(sacc[mt][nt][3] - mn2); rs2 += sacc[mt][nt][3];
            }
            rs1 += __shfl_xor_sync(0xffffffffu, rs1, 1);
            rs1 += __shfl_xor_sync(0xffffffffu, rs1, 2);
            rs2 += __shfl_xor_sync(0xffffffffu, rs2, 1);
            rs2 += __shfl_xor_sync(0xffffffffu, rs2, 2);
            ls[mt][0] = ls[mt][0] * c1 + rs1;
            ls[mt][1] = ls[mt][1] * c2 + rs2;
#pragma unroll
            for (int nt = 0; nt < 8; nt++) {
                oacc[mt][nt][0] *= c1; oacc[mt][nt][1] *= c1;
                oacc[mt][nt][2] *= c2; oacc[mt][nt][3] *= c2;
            }

            // PV(mt): register-local P A-frags, own V ldsm pass
#pragma unroll
            for (int ks = 0; ks < 4; ks++) {
                uint32_t pa0 = packh2(sacc[mt][2*ks    ][0], sacc[mt][2*ks    ][1]);
                uint32_t pa1 = packh2(sacc[mt][2*ks    ][2], sacc[mt][2*ks    ][3]);
                uint32_t pa2 = packh2(sacc[mt][2*ks + 1][0], sacc[mt][2*ks + 1][1]);
                uint32_t pa3 = packh2(sacc[mt][2*ks + 1][2], sacc[mt][2*ks + 1][3]);
#pragma unroll
                for (int p = 0; p < 4; p++) {
                    uint32_t b0, b1, b2, b3;
                    ldsm4(b0, b1, b2, b3, vb + offB[p] + ks * 32);
                    mma_f16(oacc[mt][2*p    ], pa0, pa1, pa2, pa3, b0, b1);
                    mma_f16(oacc[mt][2*p + 1], pa0, pa1, pa2, pa3, b2, b3);
                }
            }
        }
    }

    // Epilogue: normalize, write fp16 [B,S,D] (feeds O-projection)
#pragma unroll
    for (int mt = 0; mt < 2; mt++) {
        float i1 = 1.0f / ls[mt][0], i2 = 1.0f / ls[mt][1];
        const int row1 = q0 + mrow + mt * 16 + r;
#pragma unroll
        for (int nt = 0; nt < 8; nt++) {
            int col = h * HS + nt * 8 + 2 * q;
            *(__half2*)&O[(size_t)(b * SEQ + row1) * DIM + col] =
                __floats2half2_rn(oacc[mt][nt][0] * i1, oacc[mt][nt][1] * i1);
            *(__half2*)&O[(size_t)(b * SEQ + row1 + 8) * DIM + col] =
                __floats2half2_rn(oacc[mt][nt][2] * i2, oacc[mt][nt][3] * i2);
        }
    }
}

// ---------------------------------------------------------------------------
extern "C" void kernel_launch(void* const* d_in, const int* in_sizes, int n_in,
                              void* d_out, int out_size)
{
    const float* x  = (const float*)d_in[0];
    const float* Wq = (const float*)d_in[1];
    const float* bq = (const float*)d_in[2];
    const float* Wk = (const float*)d_in[3];
    const float* bk = (const float*)d_in[4];
    const float* Wv = (const float*)d_in[5];
    const float* bv = (const float*)d_in[6];
    const float* Wo = (const float*)d_in[7];
    const float* bo = (const float*)d_in[8];
    float* out = (float*)d_out;

    __half *Qp, *Kp, *Vp, *Ap, *Xp, *WTp;
    cudaGetSymbolAddress((void**)&Qp,  g_Qh);
    cudaGetSymbolAddress((void**)&Kp,  g_Kh);
    cudaGetSymbolAddress((void**)&Vp,  g_Vh);
    cudaGetSymbolAddress((void**)&Ap,  g_Ah);
    cudaGetSymbolAddress((void**)&Xp,  g_Xh);
    cudaGetSymbolAddress((void**)&WTp, g_WTh);

    const int GEMM_SMEM  = 4 * HTILEB;   // 40,960
    const int FLASH_SMEM = 4 * FKV;      // 36,864
    cudaFuncSetAttribute(gemm_h,  cudaFuncAttributeMaxDynamicSharedMemorySize, GEMM_SMEM);
    cudaFuncSetAttribute(flash_h, cudaFuncAttributeMaxDynamicSharedMemorySize, FLASH_SMEM);

    conv_x_h<<<(MTOT * DIM / 4 + 255) / 256, 256>>>(x, Xp, MTOT * DIM);
    transpose_w_h<<<dim3(DIM / 32, DIM / 32, 4), dim3(32, 8)>>>(Wq, Wk, Wv, Wo, WTp);

    // hs^-0.5 * log2(e) folded into Q (softmax runs in exp2 domain)
    const float qscale = 0.125f * 1.44269504088896340736f;

    dim3 gridQKV(3 * DIM / 128, MTOT / 128);   // (18, 64)
    gemm_h<<<gridQKV, 256, GEMM_SMEM>>>(Xp, WTp, bq, bk, bv, Qp, Kp, Vp, 1, qscale);

    dim3 gridF(SEQ / 128, HEADS, BATCH);       // (16, 12, 4)
    flash_h<<<gridF, 128, FLASH_SMEM>>>(Qp, Kp, Vp, Ap);

    dim3 gridO(DIM / 128, MTOT / 128);         // (6, 64)
    gemm_h<<<gridO, 256, GEMM_SMEM>>>(Ap, WTp + 3 * DIM * DIM, bo, bo, bo,
                                      out, Kp, Vp, 0, 1.0f);
}

// round 14
// speedup vs baseline: 8.3819x; 1.0157x over previous
#include <cuda_runtime.h>
#include <cuda_fp16.h>
#include <cstdint>
#include <math.h>

#define BATCH 4
#define SEQ   2048
#define DIM   768
#define HEADS 12
#define HS    64
#define MTOT  (BATCH*SEQ)
#define GK    DIM

// Scratch (allocation-free: __device__ globals), all fp16
static __device__ __half g_Qh[BATCH*HEADS*SEQ*HS];
static __device__ __half g_Kh[BATCH*HEADS*SEQ*HS];
static __device__ __half g_Vh[BATCH*HEADS*SEQ*HS];   // [B,H,hs,S] (transposed)
static __device__ __half g_Ah[MTOT*DIM];             // attention output, fp16
static __device__ __half g_Xh[MTOT*DIM];             // fp16 x
static __device__ __half g_WTh[4*DIM*DIM];           // fp16 W^T (N x K row-major)

// ---------------------------------------------------------------------------
// Helpers
// ---------------------------------------------------------------------------
__device__ __forceinline__ uint32_t s2u(const void* p) {
    uint32_t a;
    asm("{ .reg .u64 t; cvta.to.shared.u64 t, %1; cvt.u32.u64 %0, t; }"
        : "=r"(a) : "l"(p));
    return a;
}
__device__ __forceinline__ float ex2f(float x) {
    float y;
    asm("ex2.approx.ftz.f32 %0, %1;" : "=f"(y) : "f"(x));
    return y;
}
__device__ __forceinline__ uint32_t packh2(float lo, float hi) {
    __half2 h = __floats2half2_rn(lo, hi);
    return *(uint32_t*)&h;
}
// exp2 on two packed halves (MUFU f16x2: 2 elems per op)
__device__ __forceinline__ uint32_t ex2h2(uint32_t x) {
    uint32_t y;
    asm("ex2.approx.f16x2 %0, %1;" : "=r"(y) : "r"(x));
    return y;
}
__device__ __forceinline__ uint32_t hadd2(uint32_t a, uint32_t b) {
    uint32_t d;
    asm("add.f16x2 %0, %1, %2;" : "=r"(d) : "r"(a), "r"(b));
    return d;
}
__device__ __forceinline__ void cp16(uint32_t dst, const void* src) {
    asm volatile("cp.async.cg.shared.global [%0], [%1], 16;"
                 :: "r"(dst), "l"(src) : "memory");
}
#define CP_COMMIT asm volatile("cp.async.commit_group;" ::: "memory")
#define CP_WAIT0  asm volatile("cp.async.wait_group 0;" ::: "memory")

__device__ __forceinline__ void ldsm4(uint32_t& r0, uint32_t& r1, uint32_t& r2,
                                      uint32_t& r3, uint32_t a) {
    asm volatile("ldmatrix.sync.aligned.m8n8.x4.shared.b16 {%0,%1,%2,%3}, [%4];"
        : "=r"(r0), "=r"(r1), "=r"(r2), "=r"(r3) : "r"(a));
}

// D += A * B  (m16n8k16 f16, f32 accumulate)
__device__ __forceinline__ void mma_f16(float* d, uint32_t a0, uint32_t a1,
                                        uint32_t a2, uint32_t a3,
                                        uint32_t b0, uint32_t b1) {
    asm volatile(
        "mma.sync.aligned.m16n8k16.row.col.f32.f16.f16.f32 "
        "{%0,%1,%2,%3}, {%4,%5,%6,%7}, {%8,%9}, {%0,%1,%2,%3};"
        : "+f"(d[0]), "+f"(d[1]), "+f"(d[2]), "+f"(d[3])
        : "r"(a0), "r"(a1), "r"(a2), "r"(a3), "r"(b0), "r"(b1));
}

// ---------------------------------------------------------------------------
// Prep kernels: x -> fp16; W -> fp16 transposed (N x K)
// ---------------------------------------------------------------------------
__global__ void conv_x_h(const float* __restrict__ x, __half* __restrict__ y, int n) {
    int i = (blockIdx.x * blockDim.x + threadIdx.x) * 4;
    if (i < n) {
        float4 v = *(const float4*)&x[i];
        *(__half2*)&y[i]     = __floats2half2_rn(v.x, v.y);
        *(__half2*)&y[i + 2] = __floats2half2_rn(v.z, v.w);
    }
}

__global__ void transpose_w_h(const float* __restrict__ W0, const float* __restrict__ W1,
                              const float* __restrict__ W2, const float* __restrict__ W3,
                              __half* __restrict__ WT) {
    __shared__ float t[32][33];
    const float* W = (blockIdx.z == 0) ? W0 : (blockIdx.z == 1) ? W1
                   : (blockIdx.z == 2) ? W2 : W3;
    __half* O = WT + blockIdx.z * DIM * DIM;
    int k0 = blockIdx.y * 32, n0 = blockIdx.x * 32;
    for (int r = threadIdx.y; r < 32; r += 8)
        t[r][threadIdx.x] = W[(k0 + r) * DIM + n0 + threadIdx.x];
    __syncthreads();
    for (int r = threadIdx.y; r < 32; r += 8)
        O[(n0 + r) * DIM + k0 + threadIdx.x] = __float2half_rn(t[threadIdx.x][r]);
}

// ---------------------------------------------------------------------------
// fp16 warp-MMA GEMM (unchanged)
// ---------------------------------------------------------------------------
#define HSTB   80           // smem row stride bytes (40 halves)
#define HTILEB (128*HSTB)   // 10240

__global__ __launch_bounds__(256, 2)
void gemm_h(const __half* __restrict__ A, const __half* __restrict__ Bt,
            const float* __restrict__ bias0, const float* __restrict__ bias1,
            const float* __restrict__ bias2,
            void* __restrict__ C0v, __half* __restrict__ C1, __half* __restrict__ C2,
            int fused, float qscale)
{
    extern __shared__ __half smh[];
    const int tid = threadIdx.x;
    const int wid = tid >> 5, lane = tid & 31;
    const int wm = wid & 3, wn = wid >> 2;
    const int r = lane >> 2, q = lane & 3;
    const int m0 = blockIdx.y * 128;
    const uint32_t sbase = s2u(smh);

    const int lrA = (lane & 7) + ((lane >> 3) & 1) * 8;
    const int loA = ((lane >> 4) & 1) * 16;
    const int lrB = (lane & 7) + ((lane >> 4) & 1) * 8;
    const int loB = ((lane >> 3) & 1) * 16;
    uint32_t offA[2], offB[4];
#pragma unroll
    for (int mt = 0; mt < 2; mt++)
        offA[mt] = (uint32_t)((wm * 32 + mt * 16 + lrA) * HSTB + loA);
#pragma unroll
    for (int p = 0; p < 4; p++)
        offB[p] = (uint32_t)((wn * 64 + p * 16 + lrB) * HSTB + loB);

    float acc[2][8][4];
#pragma unroll
    for (int mt = 0; mt < 2; mt++)
#pragma unroll
        for (int nt = 0; nt < 8; nt++)
#pragma unroll
            for (int j = 0; j < 4; j++) acc[mt][nt][j] = 0.f;

    const int btrow0 = blockIdx.x * 128;
    auto load_tiles = [&](int kc, int buf) {
        uint32_t ab = sbase + (uint32_t)buf * 2u * HTILEB;
        uint32_t bb = ab + HTILEB;
#pragma unroll
        for (int i = 0; i < 2; i++) {
            int e = tid + i * 256;
            int row = e >> 2, seg = e & 3;
            cp16(ab + row * HSTB + seg * 16, A  + (m0 + row) * GK + kc + seg * 8);
            cp16(bb + row * HSTB + seg * 16, Bt + (btrow0 + row) * GK + kc + seg * 8);
        }
    };

    load_tiles(0, 0);
    CP_COMMIT;

    const int NIT = GK / 32;   // 24
    for (int it = 0; it < NIT; it++) {
        CP_WAIT0;
        __syncthreads();
        if (it + 1 < NIT) { load_tiles((it + 1) * 32, (it + 1) & 1); CP_COMMIT; }

        const uint32_t baseA = sbase + (uint32_t)(it & 1) * 2u * HTILEB;
        const uint32_t baseB = baseA + HTILEB;
#pragma unroll
        for (int ks = 0; ks < 2; ks++) {
            uint32_t a[2][4];
            ldsm4(a[0][0], a[0][1], a[0][2], a[0][3], baseA + offA[0] + ks * 32);
            ldsm4(a[1][0], a[1][1], a[1][2], a[1][3], baseA + offA[1] + ks * 32);
#pragma unroll
            for (int p = 0; p < 4; p++) {
                uint32_t b0, b1, b2, b3;
                ldsm4(b0, b1, b2, b3, baseB + offB[p] + ks * 32);
                mma_f16(acc[0][2*p    ], a[0][0], a[0][1], a[0][2], a[0][3], b0, b1);
                mma_f16(acc[1][2*p    ], a[1][0], a[1][1], a[1][2], a[1][3], b0, b1);
                mma_f16(acc[0][2*p + 1], a[0][0], a[0][1], a[0][2], a[0][3], b2, b3);
                mma_f16(acc[1][2*p + 1], a[1][0], a[1][1], a[1][2], a[1][3], b2, b3);
            }
        }
    }

    int which = 0, nloc0 = blockIdx.x * 128;
    const float* bias = bias0;
    float scale = 1.f;
    if (fused) {
        which = blockIdx.x / 6;
        nloc0 = (blockIdx.x % 6) * 128;
        bias  = (which == 0) ? bias0 : (which == 1) ? bias1 : bias2;
        scale = (which == 0) ? qscale : 1.f;
    }

#pragma unroll
    for (int mt = 0; mt < 2; mt++) {
        int row = m0 + wm * 32 + mt * 16 + r;
#pragma unroll
        for (int nt = 0; nt < 8; nt++) {
            int col = nloc0 + wn * 64 + nt * 8 + 2 * q;
            float b0v = bias[col], b1v = bias[col + 1];
            float v0 = (acc[mt][nt][0] + b0v) * scale;
            float v1 = (acc[mt][nt][1] + b1v) * scale;
            float v2 = (acc[mt][nt][2] + b0v) * scale;
            float v3 = (acc[mt][nt][3] + b1v) * scale;
            if (!fused) {
                float* C0 = (float*)C0v;
                *(float2*)&C0[row * DIM + col]       = make_float2(v0, v1);
                *(float2*)&C0[(row + 8) * DIM + col] = make_float2(v2, v3);
            } else {
                int b = row >> 11;
                int h = col >> 6, d = col & 63;
                int s1 = row & 2047, s2 = s1 + 8;
                if (which < 2) {
                    __half* Cc = which ? C1 : (__half*)C0v;
                    __half* base = Cc + ((size_t)(b * HEADS + h) * SEQ) * HS + d;
                    *(__half2*)&base[s1 * HS] = __floats2half2_rn(v0, v1);
                    *(__half2*)&base[s2 * HS] = __floats2half2_rn(v2, v3);
                } else {
                    __half* base = C2 + ((size_t)(b * HEADS + h) * HS + d) * SEQ;
                    base[s1]       = __float2half_rn(v0);
                    base[SEQ + s1] = __float2half_rn(v1);
                    base[s2]       = __float2half_rn(v2);
                    base[SEQ + s2] = __float2half_rn(v3);
                }
            }
        }
    }
}

// ---------------------------------------------------------------------------
// Flash attention fp16: 4 warps x 32 q-rows (2 M-frags/warp), 128 threads.
// Softmax exponentials via ex2.approx.f16x2: halves MUFU ops, and the results
// ARE the PV A-fragments (no packh2 pass). Row sums via HADD2 tree (+f32
// finish). Pipelined: S(0) -> S(1) -> softmax(0) -> PV(0) -> softmax(1) -> PV(1).
// FA2 register-local P. smem: Ks[2]+Vs[2] = 36,864 B; Q staged via K region.
// ---------------------------------------------------------------------------
#define FH   144            // bytes per row (72 halves)
#define FKV  (64*FH)        // 9216

__global__ __launch_bounds__(128)
void flash_h(const __half* __restrict__ Q, const __half* __restrict__ K,
             const __half* __restrict__ V, __half* __restrict__ O)
{
    extern __shared__ __half fs[];

    const int tid = threadIdx.x;
    const int wid = tid >> 5, lane = tid & 31;
    const int r = lane >> 2, q = lane & 3;
    const int mrow = wid * 32;
    const int q0 = blockIdx.x * 128, h = blockIdx.y, b = blockIdx.z;

    const __half* Qg = Q + ((size_t)(b * HEADS + h) * SEQ + q0) * HS;
    const __half* Kg = K + ((size_t)(b * HEADS + h) * SEQ) * HS;
    const __half* Vg = V + ((size_t)(b * HEADS + h) * HS) * SEQ;

    const uint32_t kbase = s2u(fs);
    const uint32_t vbase = kbase + 2 * FKV;

    const int lrA = (lane & 7) + ((lane >> 3) & 1) * 8;
    const int loA = ((lane >> 4) & 1) * 16;
    const int lrB = (lane & 7) + ((lane >> 4) & 1) * 8;
    const int loB = ((lane >> 3) & 1) * 16;
    uint32_t offB[4];
#pragma unroll
    for (int p = 0; p < 4; p++)
        offB[p] = (uint32_t)((p * 16 + lrB) * FH + loB);

    // ---- Stage Q (128 x 64 halves) through the K-buffer region ----
#pragma unroll
    for (int i = 0; i < 8; i++) {
        int e = tid + i * 128;
        int row = e >> 3, seg = e & 7;
        *(uint4*)((char*)fs + row * FH + seg * 16) =
            *(const uint4*)(Qg + row * HS + seg * 8);
    }
    __syncthreads();
    uint32_t qf[2][4][4];
#pragma unroll
    for (int mt = 0; mt < 2; mt++) {
        const uint32_t offQ = (uint32_t)((mrow + mt * 16 + lrA) * FH + loA);
#pragma unroll
        for (int ks = 0; ks < 4; ks++)
            ldsm4(qf[mt][ks][0], qf[mt][ks][1], qf[mt][ks][2], qf[mt][ks][3],
                  kbase + offQ + ks * 32);
    }
    __syncthreads();   // all qf reads done before cp.async overwrites region

    auto load_kv = [&](int t, int buf) {
        uint32_t kb = kbase + (uint32_t)buf * FKV;
        uint32_t vb = vbase + (uint32_t)buf * FKV;
#pragma unroll
        for (int i = 0; i < 4; i++) {
            int e = tid + i * 128;
            int row = e >> 3, seg = e & 7;
            cp16(kb + row * FH + seg * 16, Kg + (t * 64 + row) * HS + seg * 8);
            cp16(vb + row * FH + seg * 16, Vg + row * SEQ + t * 64 + seg * 8);
        }
    };

    load_kv(0, 0);
    CP_COMMIT;

    float mx[2][2], ls[2][2];
#pragma unroll
    for (int mt = 0; mt < 2; mt++) {
        mx[mt][0] = mx[mt][1] = -1e30f;
        ls[mt][0] = ls[mt][1] = 0.f;
    }
    float oacc[2][8][4];
#pragma unroll
    for (int mt = 0; mt < 2; mt++)
#pragma unroll
        for (int nt = 0; nt < 8; nt++)
#pragma unroll
            for (int j = 0; j < 4; j++) oacc[mt][nt][j] = 0.f;

    const int NT = SEQ / 64;  // 32
    for (int t = 0; t < NT; t++) {
        CP_WAIT0;
        __syncthreads();
        if (t + 1 < NT) { load_kv(t + 1, (t + 1) & 1); CP_COMMIT; }

        const uint32_t kb = kbase + (uint32_t)(t & 1) * FKV;
        const uint32_t vb = vbase + (uint32_t)(t & 1) * FKV;

        float sacc[2][8][4];
#pragma unroll
        for (int mt = 0; mt < 2; mt++)
#pragma unroll
            for (int nt = 0; nt < 8; nt++)
#pragma unroll
                for (int j = 0; j < 4; j++) sacc[mt][nt][j] = 0.f;

        // ---- S(mt0), S(mt1): separate passes, each with its own K ldsm ----
#pragma unroll
        for (int mt = 0; mt < 2; mt++) {
#pragma unroll
            for (int ks = 0; ks < 4; ks++) {
#pragma unroll
                for (int p = 0; p < 4; p++) {
                    uint32_t b0, b1, b2, b3;
                    ldsm4(b0, b1, b2, b3, kb + offB[p] + ks * 32);
                    mma_f16(sacc[mt][2*p    ], qf[mt][ks][0], qf[mt][ks][1],
                            qf[mt][ks][2], qf[mt][ks][3], b0, b1);
                    mma_f16(sacc[mt][2*p + 1], qf[mt][ks][0], qf[mt][ks][1],
                            qf[mt][ks][2], qf[mt][ks][3], b2, b3);
                }
            }
        }

        // ---- softmax(mt) then PV(mt); exponentials in f16x2 domain ----
#pragma unroll
        for (int mt = 0; mt < 2; mt++) {
            float mt1 = -1e30f, mt2 = -1e30f;
#pragma unroll
            for (int nt = 0; nt < 8; nt++) {
                mt1 = fmaxf(mt1, fmaxf(sacc[mt][nt][0], sacc[mt][nt][1]));
                mt2 = fmaxf(mt2, fmaxf(sacc[mt][nt][2], sacc[mt][nt][3]));
            }
            mt1 = fmaxf(mt1, __shfl_xor_sync(0xffffffffu, mt1, 1));
            mt1 = fmaxf(mt1, __shfl_xor_sync(0xffffffffu, mt1, 2));
            mt2 = fmaxf(mt2, __shfl_xor_sync(0xffffffffu, mt2, 1));
            mt2 = fmaxf(mt2, __shfl_xor_sync(0xffffffffu, mt2, 2));
            float mn1 = fmaxf(mx[mt][0], mt1), mn2 = fmaxf(mx[mt][1], mt2);
            float c1 = ex2f(mx[mt][0] - mn1), c2 = ex2f(mx[mt][1] - mn2);
            mx[mt][0] = mn1; mx[mt][1] = mn2;
            const float nm1 = -mn1, nm2 = -mn2;

            // P = exp2(S - m) computed as packed f16x2; pex IS the PV A-frag
            uint32_t pex[8][2];
#pragma unroll
            for (int nt = 0; nt < 8; nt++) {
                pex[nt][0] = ex2h2(packh2(sacc[mt][nt][0] + nm1,
                                          sacc[mt][nt][1] + nm1));
                pex[nt][1] = ex2h2(packh2(sacc[mt][nt][2] + nm2,
                                          sacc[mt][nt][3] + nm2));
            }

            // Row sums: depth-3 HADD2 tree, then f32 finish + shuffle-reduce
            uint32_t s1 = hadd2(hadd2(hadd2(pex[0][0], pex[1][0]),
                                      hadd2(pex[2][0], pex[3][0])),
                                hadd2(hadd2(pex[4][0], pex[5][0]),
                                      hadd2(pex[6][0], pex[7][0])));
            uint32_t s2 = hadd2(hadd2(hadd2(pex[0][1], pex[1][1]),
                                      hadd2(pex[2][1], pex[3][1])),
                                hadd2(hadd2(pex[4][1], pex[5][1]),
                                      hadd2(pex[6][1], pex[7][1])));
            float2 f1 = __half22float2(*(__half2*)&s1);
            float2 f2 = __half22float2(*(__half2*)&s2);
            float rs1 = f1.x + f1.y, rs2 = f2.x + f2.y;
            rs1 += __shfl_xor_sync(0xffffffffu, rs1, 1);
            rs1 += __shfl_xor_sync(0xffffffffu, rs1, 2);
            rs2 += __shfl_xor_sync(0xffffffffu, rs2, 1);
            rs2 += __shfl_xor_sync(0xffffffffu, rs2, 2);
            ls[mt][0] = ls[mt][0] * c1 + rs1;
            ls[mt][1] = ls[mt][1] * c2 + rs2;
#pragma unroll
            for (int nt = 0; nt < 8; nt++) {
                oacc[mt][nt][0] *= c1; oacc[mt][nt][1] *= c1;
                oacc[mt][nt][2] *= c2; oacc[mt][nt][3] *= c2;
            }

            // PV(mt): pex registers are the A-fragments directly
#pragma unroll
            for (int ks = 0; ks < 4; ks++) {
#pragma unroll
                for (int p = 0; p < 4; p++) {
                    uint32_t b0, b1, b2, b3;
                    ldsm4(b0, b1, b2, b3, vb + offB[p] + ks * 32);
                    mma_f16(oacc[mt][2*p    ], pex[2*ks][0], pex[2*ks][1],
                            pex[2*ks + 1][0], pex[2*ks + 1][1], b0, b1);
                    mma_f16(oacc[mt][2*p + 1], pex[2*ks][0], pex[2*ks][1],
                            pex[2*ks + 1][0], pex[2*ks + 1][1], b2, b3);
                }
            }
        }
    }

    // Epilogue: normalize, write fp16 [B,S,D] (feeds O-projection)
#pragma unroll
    for (int mt = 0; mt < 2; mt++) {
        float i1 = 1.0f / ls[mt][0], i2 = 1.0f / ls[mt][1];
        const int row1 = q0 + mrow + mt * 16 + r;
#pragma unroll
        for (int nt = 0; nt < 8; nt++) {
            int col = h * HS + nt * 8 + 2 * q;
            *(__half2*)&O[(size_t)(b * SEQ + row1) * DIM + col] =
                __floats2half2_rn(oacc[mt][nt][0] * i1, oacc[mt][nt][1] * i1);
            *(__half2*)&O[(size_t)(b * SEQ + row1 + 8) * DIM + col] =
                __floats2half2_rn(oacc[mt][nt][2] * i2, oacc[mt][nt][3] * i2);
        }
    }
}

// ---------------------------------------------------------------------------
extern "C" void kernel_launch(void* const* d_in, const int* in_sizes, int n_in,
                              void* d_out, int out_size)
{
    const float* x  = (const float*)d_in[0];
    const float* Wq = (const float*)d_in[1];
    const float* bq = (const float*)d_in[2];
    const float* Wk = (const float*)d_in[3];
    const float* bk = (const float*)d_in[4];
    const float* Wv = (const float*)d_in[5];
    const float* bv = (const float*)d_in[6];
    const float* Wo = (const float*)d_in[7];
    const float* bo = (const float*)d_in[8];
    float* out = (float*)d_out;

    __half *Qp, *Kp, *Vp, *Ap, *Xp, *WTp;
    cudaGetSymbolAddress((void**)&Qp,  g_Qh);
    cudaGetSymbolAddress((void**)&Kp,  g_Kh);
    cudaGetSymbolAddress((void**)&Vp,  g_Vh);
    cudaGetSymbolAddress((void**)&Ap,  g_Ah);
    cudaGetSymbolAddress((void**)&Xp,  g_Xh);
    cudaGetSymbolAddress((void**)&WTp, g_WTh);

    const int GEMM_SMEM  = 4 * HTILEB;   // 40,960
    const int FLASH_SMEM = 4 * FKV;      // 36,864
    cudaFuncSetAttribute(gemm_h,  cudaFuncAttributeMaxDynamicSharedMemorySize, GEMM_SMEM);
    cudaFuncSetAttribute(flash_h, cudaFuncAttributeMaxDynamicSharedMemorySize, FLASH_SMEM);

    conv_x_h<<<(MTOT * DIM / 4 + 255) / 256, 256>>>(x, Xp, MTOT * DIM);
    transpose_w_h<<<dim3(DIM / 32, DIM / 32, 4), dim3(32, 8)>>>(Wq, Wk, Wv, Wo, WTp);

    // hs^-0.5 * log2(e) folded into Q (softmax runs in exp2 domain)
    const float qscale = 0.125f * 1.44269504088896340736f;

    dim3 gridQKV(3 * DIM / 128, MTOT / 128);   // (18, 64)
    gemm_h<<<gridQKV, 256, GEMM_SMEM>>>(Xp, WTp, bq, bk, bv, Qp, Kp, Vp, 1, qscale);

    dim3 gridF(SEQ / 128, HEADS, BATCH);       // (16, 12, 4)
    flash_h<<<gridF, 128, FLASH_SMEM>>>(Qp, Kp, Vp, Ap);

    dim3 gridO(DIM / 128, MTOT / 128);         // (6, 64)
    gemm_h<<<gridO, 256, GEMM_SMEM>>>(Ap, WTp + 3 * DIM * DIM, bo, bo, bo,
                                      out, Kp, Vp, 0, 1.0f);
}